// round 3
// baseline (speedup 1.0000x reference)
#include <cuda_runtime.h>

// Problem constants (fixed by setup_inputs)
#define Bb 8
#define Cc 64
#define Nn 4096
#define Ee 8
#define KSPLIT 16                      // key-dimension splits
#define KEYS (Nn / KSPLIT)             // 256 keys per split
#define QPT 8                          // queries per thread
#define QT_PER_CTA (128 * QPT)         // 1024
#define BCN ((size_t)Bb * Cc * Nn)
#define LOG2E 1.4426950408889634f

// Scratch (__device__ globals per allocation-free rule)
// fh per (b,n): f0,f0,f1,f1,...,f7,f7, h0,h0,...,h7,h7 (dup for f32x2 query-packing)
__device__ float d_fh[Bb * Nn * 32];                   // 4 MB
__device__ float d_g [Bb * Nn * 8];                    // 1 MB (pre-scaled by log2e)
__device__ float d_pacc[(size_t)KSPLIT * Bb * Nn * 8]; // 16.8 MB
__device__ float d_pden[(size_t)KSPLIT * Bb * Nn];     // 2.1 MB

// ---------------- f32x2 + ex2 helpers ----------------
__device__ __forceinline__ unsigned long long ffma2(unsigned long long a,
                                                    unsigned long long b,
                                                    unsigned long long c) {
    unsigned long long d;
    asm("fma.rn.f32x2 %0, %1, %2, %3;" : "=l"(d) : "l"(a), "l"(b), "l"(c));
    return d;
}
__device__ __forceinline__ unsigned long long fmul2(unsigned long long a,
                                                    unsigned long long b) {
    unsigned long long d;
    asm("mul.rn.f32x2 %0, %1, %2;" : "=l"(d) : "l"(a), "l"(b));
    return d;
}
__device__ __forceinline__ unsigned long long fadd2(unsigned long long a,
                                                    unsigned long long b) {
    unsigned long long d;
    asm("add.rn.f32x2 %0, %1, %2;" : "=l"(d) : "l"(a), "l"(b));
    return d;
}
__device__ __forceinline__ unsigned long long pk2(float lo, float hi) {
    unsigned long long r;
    asm("mov.b64 %0, {%1, %2};" : "=l"(r) : "f"(lo), "f"(hi));
    return r;
}
__device__ __forceinline__ void upk2(unsigned long long v, float& lo, float& hi) {
    asm("mov.b64 {%0, %1}, %2;" : "=f"(lo), "=f"(hi) : "l"(v));
}
__device__ __forceinline__ float ex2f(float x) {
    float y;
    asm("ex2.approx.f32 %0, %1;" : "=f"(y) : "f"(x));
    return y;
}

// ---------------- Kernel A: projections f, g, h --------------------------
// grid (Nn/128, Bb), block 512: 128 pixels x 4 channel-quarters, smem combine.
__global__ __launch_bounds__(512) void proj_kernel(
    const float* __restrict__ x,
    const float* __restrict__ Wk, const float* __restrict__ bk,
    const float* __restrict__ Wq, const float* __restrict__ bq,
    const float* __restrict__ Wv, const float* __restrict__ bv)
{
    __shared__ float wks[512], wqs[512], wvs[512];
    __shared__ float red[3][24][128];   // parts 1..3 stage their partials
    const int t    = threadIdx.x;
    const int px   = t & 127;
    const int part = t >> 7;            // 0..3, owns channels [16*part, 16*part+16)
    const int b    = blockIdx.y;
    const int n    = blockIdx.x * 128 + px;

    wks[t] = Wk[t];
    wqs[t] = Wq[t] * LOG2E;             // fold log2e into query path
    wvs[t] = Wv[t];
    __syncthreads();

    float f[8], g[8], h[8];
    #pragma unroll
    for (int e = 0; e < 8; e++) { f[e] = 0.f; g[e] = 0.f; h[e] = 0.f; }

    const float* xp = &x[(size_t)b * 64 * Nn + n];
    #pragma unroll
    for (int i = 0; i < 16; i++) {
        const int c = part * 16 + i;
        const float xv = xp[(size_t)c * Nn];
        #pragma unroll
        for (int e = 0; e < 8; e++) {
            f[e] = fmaf(wks[e * 64 + c], xv, f[e]);
            g[e] = fmaf(wqs[e * 64 + c], xv, g[e]);
            h[e] = fmaf(wvs[e * 64 + c], xv, h[e]);
        }
    }

    if (part > 0) {
        #pragma unroll
        for (int e = 0; e < 8; e++) {
            red[part - 1][e][px]      = f[e];
            red[part - 1][8 + e][px]  = g[e];
            red[part - 1][16 + e][px] = h[e];
        }
    }
    __syncthreads();

    if (part == 0) {
        #pragma unroll
        for (int e = 0; e < 8; e++) {
            f[e] += red[0][e][px]      + red[1][e][px]      + red[2][e][px]      + bk[e];
            g[e] += red[0][8 + e][px]  + red[1][8 + e][px]  + red[2][8 + e][px]  + bq[e] * LOG2E;
            h[e] += red[0][16 + e][px] + red[1][16 + e][px] + red[2][16 + e][px] + bv[e];
        }
        float4* fhp = (float4*)&d_fh[(size_t)(b * Nn + n) * 32];
        #pragma unroll
        for (int j = 0; j < 4; j++)
            fhp[j]     = make_float4(f[2*j], f[2*j], f[2*j+1], f[2*j+1]);
        #pragma unroll
        for (int j = 0; j < 4; j++)
            fhp[4 + j] = make_float4(h[2*j], h[2*j], h[2*j+1], h[2*j+1]);
        float4* gp = (float4*)&d_g[(size_t)(b * Nn + n) * 8];
        gp[0] = make_float4(g[0], g[1], g[2], g[3]);
        gp[1] = make_float4(g[4], g[5], g[6], g[7]);
    }
}

// ---------------- Kernel B: fused attention core (split-K) ---------------
// grid (KSPLIT, Nn/QT_PER_CTA, Bb) = (16,4,8), block 128.
// Thread owns 8 queries as 4 query-packed f32x2 pairs; 256-key split in smem.
__global__ __launch_bounds__(128, 2) void attn_kernel()
{
    __shared__ __align__(16) float sm[KEYS * 32];      // 32 KB
    const int t  = threadIdx.x;
    const int ks = blockIdx.x;
    const int qt = blockIdx.y;
    const int b  = blockIdx.z;
    const int m0 = qt * QT_PER_CTA + t * QPT;

    // Stage all keys for this split: 2048 float4, 16 per thread (coalesced)
    {
        const float4* src = (const float4*)&d_fh[(size_t)(b * Nn + ks * KEYS) * 32];
        float4* dst = (float4*)sm;
        #pragma unroll
        for (int j = 0; j < 16; j++) dst[j * 128 + t] = src[j * 128 + t];
    }

    // 4 query pairs (already scaled by log2e)
    unsigned long long g2[4][8];
    {
        const float* gp = &d_g[(size_t)(b * Nn + m0) * 8];
        #pragma unroll
        for (int p = 0; p < 4; p++)
            #pragma unroll
            for (int e = 0; e < 8; e++)
                g2[p][e] = pk2(gp[(2 * p) * 8 + e], gp[(2 * p + 1) * 8 + e]);
    }

    unsigned long long acc2[4][8];
    unsigned long long den2[4] = {0ull, 0ull, 0ull, 0ull};
    #pragma unroll
    for (int p = 0; p < 4; p++)
        #pragma unroll
        for (int e = 0; e < 8; e++) acc2[p][e] = 0ull;

    __syncthreads();

    #pragma unroll 1
    for (int k = 0; k < KEYS; k++) {
        const ulonglong2* row = (const ulonglong2*)&sm[k * 32];
        const ulonglong2 f01 = row[0], f23 = row[1], f45 = row[2], f67 = row[3];

        unsigned long long s2[4];
        #pragma unroll
        for (int p = 0; p < 4; p++) {
            unsigned long long s = fmul2(f01.x, g2[p][0]);
            s = ffma2(f01.y, g2[p][1], s);
            s = ffma2(f23.x, g2[p][2], s);
            s = ffma2(f23.y, g2[p][3], s);
            s = ffma2(f45.x, g2[p][4], s);
            s = ffma2(f45.y, g2[p][5], s);
            s = ffma2(f67.x, g2[p][6], s);
            s = ffma2(f67.y, g2[p][7], s);
            s2[p] = s;
        }

        unsigned long long p2[4];
        #pragma unroll
        for (int p = 0; p < 4; p++) {
            float a, c;
            upk2(s2[p], a, c);
            p2[p] = pk2(ex2f(a), ex2f(c));
            den2[p] = fadd2(den2[p], p2[p]);
        }

        const ulonglong2 h01 = row[4], h23 = row[5], h45 = row[6], h67 = row[7];
        #pragma unroll
        for (int p = 0; p < 4; p++) {
            acc2[p][0] = ffma2(h01.x, p2[p], acc2[p][0]);
            acc2[p][1] = ffma2(h01.y, p2[p], acc2[p][1]);
            acc2[p][2] = ffma2(h23.x, p2[p], acc2[p][2]);
            acc2[p][3] = ffma2(h23.y, p2[p], acc2[p][3]);
            acc2[p][4] = ffma2(h45.x, p2[p], acc2[p][4]);
            acc2[p][5] = ffma2(h45.y, p2[p], acc2[p][5]);
            acc2[p][6] = ffma2(h67.x, p2[p], acc2[p][6]);
            acc2[p][7] = ffma2(h67.y, p2[p], acc2[p][7]);
        }
    }

    // Write partials (aligned float4 acc, scalar den) for 8 queries
    const size_t base = ((size_t)ks * Bb + b) * Nn;
    #pragma unroll
    for (int p = 0; p < 4; p++) {
        float lo[8], hi[8], dl, dh;
        #pragma unroll
        for (int e = 0; e < 8; e++) upk2(acc2[p][e], lo[e], hi[e]);
        upk2(den2[p], dl, dh);
        const int mA = m0 + 2 * p, mB = mA + 1;
        float4* oA = (float4*)&d_pacc[(base + mA) * 8];
        float4* oB = (float4*)&d_pacc[(base + mB) * 8];
        oA[0] = make_float4(lo[0], lo[1], lo[2], lo[3]);
        oA[1] = make_float4(lo[4], lo[5], lo[6], lo[7]);
        oB[0] = make_float4(hi[0], hi[1], hi[2], hi[3]);
        oB[1] = make_float4(hi[4], hi[5], hi[6], hi[7]);
        d_pden[base + mA] = dl;
        d_pden[base + mB] = dh;
    }
}

// ---------------- Kernel C: combine splits, Wo projection, y -------------
// grid (Nn/128, Bb), block 256: lower half combines, both halves project.
__global__ __launch_bounds__(256) void out_kernel(
    const float* __restrict__ x,
    const float* __restrict__ Wo, const float* __restrict__ bo,
    const float* __restrict__ gamma, float* __restrict__ out)
{
    __shared__ float vs[8 * 128];
    __shared__ float wos[512], bos[64];
    const int t    = threadIdx.x;
    const int px   = t & 127;
    const int half = t >> 7;
    const int b    = blockIdx.y;
    const int m    = blockIdx.x * 128 + px;

    for (int i = t; i < 512; i += 256) wos[i] = Wo[i];
    if (t < 64) bos[t] = bo[t];

    if (half == 0) {
        float acc[8] = {0,0,0,0,0,0,0,0};
        float den = 0.0f;
        #pragma unroll
        for (int s = 0; s < KSPLIT; s++) {
            const size_t base = ((size_t)s * Bb + b) * Nn + m;
            const float4* pp = (const float4*)&d_pacc[base * 8];
            const float4 a0 = pp[0], a1 = pp[1];
            acc[0] += a0.x; acc[1] += a0.y; acc[2] += a0.z; acc[3] += a0.w;
            acc[4] += a1.x; acc[5] += a1.y; acc[6] += a1.z; acc[7] += a1.w;
            den += d_pden[base];
        }
        const float inv = 1.0f / den;
        #pragma unroll
        for (int e = 0; e < 8; e++) vs[e * 128 + px] = acc[e] * inv;
    }
    __syncthreads();

    const float gam = gamma[0];
    #pragma unroll 4
    for (int ci = 0; ci < 32; ci++) {
        const int c = half * 32 + ci;
        float o = bos[c];
        #pragma unroll
        for (int e = 0; e < 8; e++) o = fmaf(wos[c * 8 + e], vs[e * 128 + px], o);
        const size_t idx = ((size_t)b * 64 + c) * Nn + m;
        out[BCN + idx] = o;                    // o
        out[idx]       = fmaf(gam, o, x[idx]); // y = gamma*o + x
    }
    if (b == 0 && m == 0 && half == 0) out[2 * BCN] = gam;  // gamma scalar
}

// ---------------- Launch --------------------------------------------------
extern "C" void kernel_launch(void* const* d_in, const int* in_sizes, int n_in,
                              void* d_out, int out_size)
{
    const float* x     = (const float*)d_in[0];
    const float* Wk    = (const float*)d_in[1];
    const float* bk    = (const float*)d_in[2];
    const float* Wq    = (const float*)d_in[3];
    const float* bq    = (const float*)d_in[4];
    const float* Wv    = (const float*)d_in[5];
    const float* bv    = (const float*)d_in[6];
    const float* Wo    = (const float*)d_in[7];
    const float* bo    = (const float*)d_in[8];
    const float* gamma = (const float*)d_in[9];
    float* out = (float*)d_out;

    proj_kernel<<<dim3(Nn / 128, Bb), 512>>>(x, Wk, bk, Wq, bq, Wv, bv);
    attn_kernel<<<dim3(KSPLIT, Nn / QT_PER_CTA, Bb), 128>>>();
    out_kernel<<<dim3(Nn / 128, Bb), 256>>>(x, Wo, bo, gamma, out);
}

// round 4
// speedup vs baseline: 1.1848x; 1.1848x over previous
#include <cuda_runtime.h>

// Problem constants (fixed by setup_inputs)
#define Bb 8
#define Cc 64
#define Nn 4096
#define Ee 8
#define KSPLIT 16                      // key-dimension splits
#define KEYS (Nn / KSPLIT)             // 256 keys per split
#define QPT 4                          // queries per thread
#define QT_PER_CTA (128 * QPT)         // 512
#define BCN ((size_t)Bb * Cc * Nn)
#define LOG2E 1.4426950408889634f

// Scratch (__device__ globals per allocation-free rule)
// fh per (b,n): f0,f0,f1,f1,...,f7,f7, h0,h0,...,h7,h7 (dup for f32x2 query-packing)
__device__ float d_fh[Bb * Nn * 32];                   // 4 MB
__device__ float d_g [Bb * Nn * 8];                    // 1 MB (pre-scaled by log2e)
__device__ float d_pacc[(size_t)KSPLIT * Bb * Nn * 8]; // 16.8 MB
__device__ float d_pden[(size_t)KSPLIT * Bb * Nn];     // 2.1 MB

// ---------------- f32x2 + ex2 helpers ----------------
__device__ __forceinline__ unsigned long long ffma2(unsigned long long a,
                                                    unsigned long long b,
                                                    unsigned long long c) {
    unsigned long long d;
    asm("fma.rn.f32x2 %0, %1, %2, %3;" : "=l"(d) : "l"(a), "l"(b), "l"(c));
    return d;
}
__device__ __forceinline__ unsigned long long fmul2(unsigned long long a,
                                                    unsigned long long b) {
    unsigned long long d;
    asm("mul.rn.f32x2 %0, %1, %2;" : "=l"(d) : "l"(a), "l"(b));
    return d;
}
__device__ __forceinline__ unsigned long long fadd2(unsigned long long a,
                                                    unsigned long long b) {
    unsigned long long d;
    asm("add.rn.f32x2 %0, %1, %2;" : "=l"(d) : "l"(a), "l"(b));
    return d;
}
__device__ __forceinline__ unsigned long long pk2(float lo, float hi) {
    unsigned long long r;
    asm("mov.b64 %0, {%1, %2};" : "=l"(r) : "f"(lo), "f"(hi));
    return r;
}
__device__ __forceinline__ void upk2(unsigned long long v, float& lo, float& hi) {
    asm("mov.b64 {%0, %1}, %2;" : "=f"(lo), "=f"(hi) : "l"(v));
}
__device__ __forceinline__ float ex2f(float x) {
    float y;
    asm("ex2.approx.f32 %0, %1;" : "=f"(y) : "f"(x));
    return y;
}

// ---------------- Kernel A: projections f, g, h --------------------------
// grid (Nn/128, Bb), block 512: 128 pixels x 4 channel-quarters, smem combine.
__global__ __launch_bounds__(512, 2) void proj_kernel(
    const float* __restrict__ x,
    const float* __restrict__ Wk, const float* __restrict__ bk,
    const float* __restrict__ Wq, const float* __restrict__ bq,
    const float* __restrict__ Wv, const float* __restrict__ bv)
{
    __shared__ float wks[512], wqs[512], wvs[512];
    __shared__ float red[3][24][128];   // parts 1..3 stage their partials
    const int t    = threadIdx.x;
    const int px   = t & 127;
    const int part = t >> 7;            // 0..3, owns channels [16*part, 16*part+16)
    const int b    = blockIdx.y;
    const int n    = blockIdx.x * 128 + px;

    wks[t] = Wk[t];
    wqs[t] = Wq[t] * LOG2E;             // fold log2e into query path
    wvs[t] = Wv[t];
    __syncthreads();

    float f[8], g[8], h[8];
    #pragma unroll
    for (int e = 0; e < 8; e++) { f[e] = 0.f; g[e] = 0.f; h[e] = 0.f; }

    const float* xp = &x[(size_t)b * 64 * Nn + n];
    #pragma unroll 4
    for (int i = 0; i < 16; i++) {
        const int c = part * 16 + i;
        const float xv = xp[(size_t)c * Nn];
        #pragma unroll
        for (int e = 0; e < 8; e++) {
            f[e] = fmaf(wks[e * 64 + c], xv, f[e]);
            g[e] = fmaf(wqs[e * 64 + c], xv, g[e]);
            h[e] = fmaf(wvs[e * 64 + c], xv, h[e]);
        }
    }

    if (part > 0) {
        #pragma unroll
        for (int e = 0; e < 8; e++) {
            red[part - 1][e][px]      = f[e];
            red[part - 1][8 + e][px]  = g[e];
            red[part - 1][16 + e][px] = h[e];
        }
    }
    __syncthreads();

    if (part == 0) {
        #pragma unroll
        for (int e = 0; e < 8; e++) {
            f[e] += red[0][e][px]      + red[1][e][px]      + red[2][e][px]      + bk[e];
            g[e] += red[0][8 + e][px]  + red[1][8 + e][px]  + red[2][8 + e][px]  + bq[e] * LOG2E;
            h[e] += red[0][16 + e][px] + red[1][16 + e][px] + red[2][16 + e][px] + bv[e];
        }
        float4* fhp = (float4*)&d_fh[(size_t)(b * Nn + n) * 32];
        #pragma unroll
        for (int j = 0; j < 4; j++)
            fhp[j]     = make_float4(f[2*j], f[2*j], f[2*j+1], f[2*j+1]);
        #pragma unroll
        for (int j = 0; j < 4; j++)
            fhp[4 + j] = make_float4(h[2*j], h[2*j], h[2*j+1], h[2*j+1]);
        float4* gp = (float4*)&d_g[(size_t)(b * Nn + n) * 8];
        gp[0] = make_float4(g[0], g[1], g[2], g[3]);
        gp[1] = make_float4(g[4], g[5], g[6], g[7]);
    }
}

// ---------------- Kernel B: fused attention core (split-K) ---------------
// grid (KSPLIT, Nn/QT_PER_CTA, Bb) = (16,8,8), block 128.
// Thread owns 4 queries as 2 query-packed f32x2 pairs; 256-key split in smem.
__global__ __launch_bounds__(128, 4) void attn_kernel()
{
    __shared__ __align__(16) float sm[KEYS * 32];      // 32 KB
    const int t  = threadIdx.x;
    const int ks = blockIdx.x;
    const int qt = blockIdx.y;
    const int b  = blockIdx.z;
    const int m0 = qt * QT_PER_CTA + t * QPT;

    // Stage all keys for this split: 2048 float4, 16 per thread (coalesced)
    {
        const float4* src = (const float4*)&d_fh[(size_t)(b * Nn + ks * KEYS) * 32];
        float4* dst = (float4*)sm;
        #pragma unroll
        for (int j = 0; j < 16; j++) dst[j * 128 + t] = src[j * 128 + t];
    }

    // 2 query pairs (already scaled by log2e)
    unsigned long long g2[2][8];
    {
        const float* gp = &d_g[(size_t)(b * Nn + m0) * 8];
        #pragma unroll
        for (int p = 0; p < 2; p++)
            #pragma unroll
            for (int e = 0; e < 8; e++)
                g2[p][e] = pk2(gp[(2 * p) * 8 + e], gp[(2 * p + 1) * 8 + e]);
    }

    unsigned long long acc2[2][8];
    unsigned long long den2[2] = {0ull, 0ull};
    #pragma unroll
    for (int p = 0; p < 2; p++)
        #pragma unroll
        for (int e = 0; e < 8; e++) acc2[p][e] = 0ull;

    __syncthreads();

    #pragma unroll 4
    for (int k = 0; k < KEYS; k++) {
        const ulonglong2* row = (const ulonglong2*)&sm[k * 32];
        const ulonglong2 f01 = row[0], f23 = row[1], f45 = row[2], f67 = row[3];

        unsigned long long s2[2];
        #pragma unroll
        for (int p = 0; p < 2; p++) {
            unsigned long long s = fmul2(f01.x, g2[p][0]);
            s = ffma2(f01.y, g2[p][1], s);
            s = ffma2(f23.x, g2[p][2], s);
            s = ffma2(f23.y, g2[p][3], s);
            s = ffma2(f45.x, g2[p][4], s);
            s = ffma2(f45.y, g2[p][5], s);
            s = ffma2(f67.x, g2[p][6], s);
            s = ffma2(f67.y, g2[p][7], s);
            s2[p] = s;
        }

        unsigned long long p2[2];
        #pragma unroll
        for (int p = 0; p < 2; p++) {
            float a, c;
            upk2(s2[p], a, c);
            p2[p] = pk2(ex2f(a), ex2f(c));
            den2[p] = fadd2(den2[p], p2[p]);
        }

        const ulonglong2 h01 = row[4], h23 = row[5], h45 = row[6], h67 = row[7];
        #pragma unroll
        for (int p = 0; p < 2; p++) {
            acc2[p][0] = ffma2(h01.x, p2[p], acc2[p][0]);
            acc2[p][1] = ffma2(h01.y, p2[p], acc2[p][1]);
            acc2[p][2] = ffma2(h23.x, p2[p], acc2[p][2]);
            acc2[p][3] = ffma2(h23.y, p2[p], acc2[p][3]);
            acc2[p][4] = ffma2(h45.x, p2[p], acc2[p][4]);
            acc2[p][5] = ffma2(h45.y, p2[p], acc2[p][5]);
            acc2[p][6] = ffma2(h67.x, p2[p], acc2[p][6]);
            acc2[p][7] = ffma2(h67.y, p2[p], acc2[p][7]);
        }
    }

    // Write partials (aligned float4 acc, scalar den) for 4 queries
    const size_t base = ((size_t)ks * Bb + b) * Nn;
    #pragma unroll
    for (int p = 0; p < 2; p++) {
        float lo[8], hi[8], dl, dh;
        #pragma unroll
        for (int e = 0; e < 8; e++) upk2(acc2[p][e], lo[e], hi[e]);
        upk2(den2[p], dl, dh);
        const int mA = m0 + 2 * p, mB = mA + 1;
        float4* oA = (float4*)&d_pacc[(base + mA) * 8];
        float4* oB = (float4*)&d_pacc[(base + mB) * 8];
        oA[0] = make_float4(lo[0], lo[1], lo[2], lo[3]);
        oA[1] = make_float4(lo[4], lo[5], lo[6], lo[7]);
        oB[0] = make_float4(hi[0], hi[1], hi[2], hi[3]);
        oB[1] = make_float4(hi[4], hi[5], hi[6], hi[7]);
        d_pden[base + mA] = dl;
        d_pden[base + mB] = dh;
    }
}

// ---------------- Kernel C: combine splits, Wo projection, y -------------
// grid (Nn/128, Bb), block 256: lower half combines, both halves project.
__global__ __launch_bounds__(256) void out_kernel(
    const float* __restrict__ x,
    const float* __restrict__ Wo, const float* __restrict__ bo,
    const float* __restrict__ gamma, float* __restrict__ out)
{
    __shared__ float vs[8 * 128];
    __shared__ float wos[512], bos[64];
    const int t    = threadIdx.x;
    const int px   = t & 127;
    const int half = t >> 7;
    const int b    = blockIdx.y;
    const int m    = blockIdx.x * 128 + px;

    for (int i = t; i < 512; i += 256) wos[i] = Wo[i];
    if (t < 64) bos[t] = bo[t];

    if (half == 0) {
        float acc[8] = {0,0,0,0,0,0,0,0};
        float den = 0.0f;
        #pragma unroll
        for (int s = 0; s < KSPLIT; s++) {
            const size_t base = ((size_t)s * Bb + b) * Nn + m;
            const float4* pp = (const float4*)&d_pacc[base * 8];
            const float4 a0 = pp[0], a1 = pp[1];
            acc[0] += a0.x; acc[1] += a0.y; acc[2] += a0.z; acc[3] += a0.w;
            acc[4] += a1.x; acc[5] += a1.y; acc[6] += a1.z; acc[7] += a1.w;
            den += d_pden[base];
        }
        const float inv = 1.0f / den;
        #pragma unroll
        for (int e = 0; e < 8; e++) vs[e * 128 + px] = acc[e] * inv;
    }
    __syncthreads();

    const float gam = gamma[0];
    #pragma unroll 4
    for (int ci = 0; ci < 32; ci++) {
        const int c = half * 32 + ci;
        float o = bos[c];
        #pragma unroll
        for (int e = 0; e < 8; e++) o = fmaf(wos[c * 8 + e], vs[e * 128 + px], o);
        const size_t idx = ((size_t)b * 64 + c) * Nn + m;
        out[BCN + idx] = o;                    // o
        out[idx]       = fmaf(gam, o, x[idx]); // y = gamma*o + x
    }
    if (b == 0 && m == 0 && half == 0) out[2 * BCN] = gam;  // gamma scalar
}

// ---------------- Launch --------------------------------------------------
extern "C" void kernel_launch(void* const* d_in, const int* in_sizes, int n_in,
                              void* d_out, int out_size)
{
    const float* x     = (const float*)d_in[0];
    const float* Wk    = (const float*)d_in[1];
    const float* bk    = (const float*)d_in[2];
    const float* Wq    = (const float*)d_in[3];
    const float* bq    = (const float*)d_in[4];
    const float* Wv    = (const float*)d_in[5];
    const float* bv    = (const float*)d_in[6];
    const float* Wo    = (const float*)d_in[7];
    const float* bo    = (const float*)d_in[8];
    const float* gamma = (const float*)d_in[9];
    float* out = (float*)d_out;

    proj_kernel<<<dim3(Nn / 128, Bb), 512>>>(x, Wk, bk, Wq, bq, Wv, bv);
    attn_kernel<<<dim3(KSPLIT, Nn / QT_PER_CTA, Bb), 128>>>();
    out_kernel<<<dim3(Nn / 128, Bb), 256>>>(x, Wo, bo, gamma, out);
}

// round 6
// speedup vs baseline: 2.0346x; 1.7173x over previous
#include <cuda_runtime.h>
#include <cuda_bf16.h>
#include <cstdint>

// Problem constants
#define Bb 8
#define Cc 64
#define Nn 4096
#define KSPLIT 4
#define KPC (Nn / KSPLIT)       // 1024 keys per CTA
#define CHK 128                 // keys per chunk
#define NCHK (KPC / CHK)        // 8 chunks
#define BCN ((size_t)Bb * Cc * Nn)
#define LOG2E 1.4426950408889634f

// Scratch
__device__ float d_f[Bb * Nn * 8];
__device__ float d_h[Bb * Nn * 8];
__device__ float d_g[Bb * Nn * 8];   // pre-scaled by log2e
__device__ float d_pacc[(size_t)KSPLIT * Bb * Nn * 8];
__device__ float d_pden[(size_t)KSPLIT * Bb * Nn];

// ---------------- helpers ----------------
__device__ __forceinline__ float ex2f(float x) {
    float y; asm("ex2.approx.f32 %0, %1;" : "=f"(y) : "f"(x)); return y;
}
// Dekker split of 2 floats into bf16 hi-pair word (lo16=a, hi16=b) and lo-pair word
__device__ __forceinline__ void pack_split(float a, float b, uint32_t& hw, uint32_t& lw) {
    uint32_t h;
    asm("cvt.rn.bf16x2.f32 %0, %1, %2;" : "=r"(h) : "f"(b), "f"(a));
    const float ah = __uint_as_float(h << 16);
    const float bh = __uint_as_float(h & 0xFFFF0000u);
    const float al = a - ah, bl = b - bh;
    uint32_t l;
    asm("cvt.rn.bf16x2.f32 %0, %1, %2;" : "=r"(l) : "f"(bl), "f"(al));
    hw = h; lw = l;
}
// m16n8k16 bf16 MMA, row.col, f32 accumulate (D += A*B)
__device__ __forceinline__ void mma16816(float* d, const uint32_t* a,
                                         uint32_t b0, uint32_t b1) {
    asm volatile("mma.sync.aligned.m16n8k16.row.col.f32.bf16.bf16.f32 "
        "{%0,%1,%2,%3}, {%4,%5,%6,%7}, {%8,%9}, {%0,%1,%2,%3};"
        : "+f"(d[0]), "+f"(d[1]), "+f"(d[2]), "+f"(d[3])
        : "r"(a[0]), "r"(a[1]), "r"(a[2]), "r"(a[3]), "r"(b0), "r"(b1));
}

// ---------------- Kernel A: projections f, g, h ---------------------------
__global__ __launch_bounds__(512) void proj_kernel(
    const float* __restrict__ x,
    const float* __restrict__ Wk, const float* __restrict__ bk,
    const float* __restrict__ Wq, const float* __restrict__ bq,
    const float* __restrict__ Wv, const float* __restrict__ bv)
{
    __shared__ float wks[512], wqs[512], wvs[512];
    __shared__ float red[3][24][128];
    const int t = threadIdx.x, px = t & 127, part = t >> 7;
    const int b = blockIdx.y;
    const int n = blockIdx.x * 128 + px;

    wks[t] = Wk[t];
    wqs[t] = Wq[t] * LOG2E;
    wvs[t] = Wv[t];
    __syncthreads();

    float f[8], g[8], h[8];
    #pragma unroll
    for (int e = 0; e < 8; e++) { f[e] = 0.f; g[e] = 0.f; h[e] = 0.f; }

    const float* xp = &x[(size_t)b * 64 * Nn + n];
    #pragma unroll
    for (int i = 0; i < 16; i++) {
        const int c = part * 16 + i;
        const float xv = xp[(size_t)c * Nn];
        #pragma unroll
        for (int e = 0; e < 8; e++) {
            f[e] = fmaf(wks[e * 64 + c], xv, f[e]);
            g[e] = fmaf(wqs[e * 64 + c], xv, g[e]);
            h[e] = fmaf(wvs[e * 64 + c], xv, h[e]);
        }
    }
    if (part > 0) {
        #pragma unroll
        for (int e = 0; e < 8; e++) {
            red[part - 1][e][px]      = f[e];
            red[part - 1][8 + e][px]  = g[e];
            red[part - 1][16 + e][px] = h[e];
        }
    }
    __syncthreads();
    if (part == 0) {
        #pragma unroll
        for (int e = 0; e < 8; e++) {
            f[e] += red[0][e][px]      + red[1][e][px]      + red[2][e][px]      + bk[e];
            g[e] += red[0][8 + e][px]  + red[1][8 + e][px]  + red[2][8 + e][px]  + bq[e] * LOG2E;
            h[e] += red[0][16 + e][px] + red[1][16 + e][px] + red[2][16 + e][px] + bv[e];
        }
        const size_t o = (size_t)(b * Nn + n) * 8;
        float4* fp = (float4*)&d_f[o];
        fp[0] = make_float4(f[0], f[1], f[2], f[3]);
        fp[1] = make_float4(f[4], f[5], f[6], f[7]);
        float4* hp = (float4*)&d_h[o];
        hp[0] = make_float4(h[0], h[1], h[2], h[3]);
        hp[1] = make_float4(h[4], h[5], h[6], h[7]);
        float4* gp = (float4*)&d_g[o];
        gp[0] = make_float4(g[0], g[1], g[2], g[3]);
        gp[1] = make_float4(g[4], g[5], g[6], g[7]);
    }
}

// ---------------- Kernel B: FA2-style HMMA attention ----------------------
// grid (KSPLIT, Nn/128, Bb), block 128 (4 warps, 32 queries each).
__global__ __launch_bounds__(128) void attn_kernel()
{
    __shared__ __align__(16) uint32_t s_fh[2][128 * 4];  // f_hi: [key][4 bf16x2]
    __shared__ __align__(16) uint32_t s_fl[2][128 * 4];  // f_lo
    __shared__ __align__(16) uint32_t s_hT[2][16 * 68];  // H^T: 16 dim-rows (hh 0-7, hl 8-15), 68 u32 stride

    const int t = threadIdx.x, wid = t >> 5, lane = t & 31;
    const int ks = blockIdx.x, qt = blockIdx.y, b = blockIdx.z;
    const int kbase = ks * KPC;
    const int r = lane >> 2, c2 = (lane & 3) * 2;

    // G A-fragments (once): A[16q x 16] = [g_hi(8) | g_lo(8)]
    uint32_t aG[2][4];
    #pragma unroll
    for (int mt = 0; mt < 2; mt++) {
        #pragma unroll
        for (int hh = 0; hh < 2; hh++) {
            const int q = qt * 128 + wid * 32 + mt * 16 + r + hh * 8;
            const float2 gv = *(const float2*)&d_g[((size_t)b * Nn + q) * 8 + c2];
            uint32_t hw, lw;
            pack_split(gv.x, gv.y, hw, lw);
            aG[mt][hh]     = hw;   // a0/a1: rows r, r+8; k = emb 0..7 (g_hi)
            aG[mt][2 + hh] = lw;   // a2/a3: k = emb 8..15 (g_lo)
        }
    }

    float vacc[2][4] = {{0.f,0.f,0.f,0.f},{0.f,0.f,0.f,0.f}};
    float den[2][2]  = {{0.f,0.f},{0.f,0.f}};

    auto load_chunk = [&](int ch, int buf) {
        const size_t kg = (size_t)b * Nn + kbase + ch * CHK;
        {   // F: thread t <-> key t
            const float4* fp = (const float4*)&d_f[(kg + t) * 8];
            const float4 f0 = fp[0], f1 = fp[1];
            uint32_t h0,l0,h1,l1,h2,l2,h3,l3;
            pack_split(f0.x, f0.y, h0, l0);
            pack_split(f0.z, f0.w, h1, l1);
            pack_split(f1.x, f1.y, h2, l2);
            pack_split(f1.z, f1.w, h3, l3);
            *(uint4*)&s_fh[buf][t * 4] = make_uint4(h0, h1, h2, h3);
            *(uint4*)&s_fl[buf][t * 4] = make_uint4(l0, l1, l2, l3);
        }
        if (t < 64) {  // H: thread t <-> keys 2t, 2t+1, transpose-store
            const float4* ha = (const float4*)&d_h[(kg + 2 * t) * 8];
            const float4* hb = (const float4*)&d_h[(kg + 2 * t + 1) * 8];
            const float4 a0 = ha[0], a1 = ha[1], b0 = hb[0], b1 = hb[1];
            const float av[8] = {a0.x,a0.y,a0.z,a0.w,a1.x,a1.y,a1.z,a1.w};
            const float bv[8] = {b0.x,b0.y,b0.z,b0.w,b1.x,b1.y,b1.z,b1.w};
            #pragma unroll
            for (int d = 0; d < 8; d++) {
                uint32_t hw, lw;
                pack_split(av[d], bv[d], hw, lw);
                s_hT[buf][d * 68 + t]       = hw;   // hh
                s_hT[buf][(8 + d) * 68 + t] = lw;   // hl
            }
        }
    };

    auto compute = [&](int buf) {
        #pragma unroll
        for (int g = 0; g < 8; g++) {          // 16-key groups
            #pragma unroll
            for (int mt = 0; mt < 2; mt++) {
                // S: two n8 tiles, exact via hi+lo
                float s[8] = {0.f,0.f,0.f,0.f,0.f,0.f,0.f,0.f};
                #pragma unroll
                for (int nt = 0; nt < 2; nt++) {
                    const int key = g * 16 + nt * 8 + r;
                    const uint32_t bh = s_fh[buf][key * 4 + (lane & 3)];
                    const uint32_t bl = s_fl[buf][key * 4 + (lane & 3)];
                    mma16816(&s[nt * 4], aG[mt], bh, bh);  // (gh+gl)*fh
                    mma16816(&s[nt * 4], aG[mt], bl, bl);  // (gh+gl)*fl
                }
                // exp
                float p[8];
                #pragma unroll
                for (int j = 0; j < 8; j++) p[j] = ex2f(s[j]);
                den[mt][0] += (p[0] + p[1]) + (p[4] + p[5]);
                den[mt][1] += (p[2] + p[3]) + (p[6] + p[7]);
                // P A-fragments (hi/lo)
                uint32_t ah[4], al[4];
                pack_split(p[0], p[1], ah[0], al[0]);
                pack_split(p[2], p[3], ah[1], al[1]);
                pack_split(p[4], p[5], ah[2], al[2]);
                pack_split(p[6], p[7], ah[3], al[3]);
                // V B-fragments from H^T
                const int kw = g * 8 + (lane & 3);   // u32 index of key pair
                const uint32_t bh0 = s_hT[buf][r * 68 + kw];
                const uint32_t bh1 = s_hT[buf][r * 68 + kw + 4];
                const uint32_t bl0 = s_hT[buf][(8 + r) * 68 + kw];
                const uint32_t bl1 = s_hT[buf][(8 + r) * 68 + kw + 4];
                mma16816(vacc[mt], ah, bh0, bh1);    // ph*hh
                mma16816(vacc[mt], al, bh0, bh1);    // pl*hh
                mma16816(vacc[mt], ah, bl0, bl1);    // ph*hl
            }
        }
    };

    load_chunk(0, 0);
    __syncthreads();
    for (int ch = 0; ch < NCHK; ch++) {
        compute(ch & 1);
        if (ch + 1 < NCHK) load_chunk(ch + 1, (ch + 1) & 1);
        __syncthreads();
    }

    // Epilogue: quad-reduce den, write partials
    const size_t base = ((size_t)ks * Bb + b) * Nn;
    #pragma unroll
    for (int mt = 0; mt < 2; mt++) {
        #pragma unroll
        for (int hh = 0; hh < 2; hh++) {
            float dsum = den[mt][hh];
            dsum += __shfl_xor_sync(0xffffffffu, dsum, 1);
            dsum += __shfl_xor_sync(0xffffffffu, dsum, 2);
            const int q = qt * 128 + wid * 32 + mt * 16 + r + hh * 8;
            *(float2*)&d_pacc[(base + q) * 8 + c2] =
                make_float2(vacc[mt][2 * hh], vacc[mt][2 * hh + 1]);
            if ((lane & 3) == 0) d_pden[base + q] = dsum;
        }
    }
}

// ---------------- Kernel C: combine splits, Wo projection, y ---------------
__global__ __launch_bounds__(256) void out_kernel(
    const float* __restrict__ x,
    const float* __restrict__ Wo, const float* __restrict__ bo,
    const float* __restrict__ gamma, float* __restrict__ out)
{
    __shared__ float vs[8 * 128];
    __shared__ float wos[512], bos[64];
    const int t = threadIdx.x, px = t & 127, half = t >> 7;
    const int b = blockIdx.y;
    const int m = blockIdx.x * 128 + px;

    for (int i = t; i < 512; i += 256) wos[i] = Wo[i];
    if (t < 64) bos[t] = bo[t];

    if (half == 0) {
        float acc[8] = {0, 0, 0, 0, 0, 0, 0, 0};
        float den = 0.0f;
        #pragma unroll
        for (int s = 0; s < KSPLIT; s++) {
            const size_t base = ((size_t)s * Bb + b) * Nn + m;
            const float4* pp = (const float4*)&d_pacc[base * 8];
            const float4 a0 = pp[0], a1 = pp[1];
            acc[0] += a0.x; acc[1] += a0.y; acc[2] += a0.z; acc[3] += a0.w;
            acc[4] += a1.x; acc[5] += a1.y; acc[6] += a1.z; acc[7] += a1.w;
            den += d_pden[base];
        }
        const float inv = 1.0f / den;
        #pragma unroll
        for (int e = 0; e < 8; e++) vs[e * 128 + px] = acc[e] * inv;
    }
    __syncthreads();

    const float gam = gamma[0];
    #pragma unroll 4
    for (int ci = 0; ci < 32; ci++) {
        const int c = half * 32 + ci;
        float o = bos[c];
        #pragma unroll
        for (int e = 0; e < 8; e++) o = fmaf(wos[c * 8 + e], vs[e * 128 + px], o);
        const size_t idx = ((size_t)b * 64 + c) * Nn + m;
        out[BCN + idx] = o;
        out[idx]       = fmaf(gam, o, x[idx]);
    }
    if (b == 0 && m == 0 && half == 0) out[2 * BCN] = gam;
}

// ---------------- Launch ----------------------------------------------------
extern "C" void kernel_launch(void* const* d_in, const int* in_sizes, int n_in,
                              void* d_out, int out_size)
{
    const float* x     = (const float*)d_in[0];
    const float* Wk    = (const float*)d_in[1];
    const float* bk    = (const float*)d_in[2];
    const float* Wq    = (const float*)d_in[3];
    const float* bq    = (const float*)d_in[4];
    const float* Wv    = (const float*)d_in[5];
    const float* bv    = (const float*)d_in[6];
    const float* Wo    = (const float*)d_in[7];
    const float* bo    = (const float*)d_in[8];
    const float* gamma = (const float*)d_in[9];
    float* out = (float*)d_out;

    proj_kernel<<<dim3(Nn / 128, Bb), 512>>>(x, Wk, bk, Wq, bq, Wv, bv);
    attn_kernel<<<dim3(KSPLIT, Nn / 128, Bb), 128>>>();
    out_kernel<<<dim3(Nn / 128, Bb), 256>>>(x, Wo, bo, gamma, out);
}

// round 8
// speedup vs baseline: 2.2329x; 1.0975x over previous
#include <cuda_runtime.h>
#include <cuda_bf16.h>
#include <cstdint>

// Problem constants
#define Bb 8
#define Cc 64
#define Nn 4096
#define KSPLIT 4
#define KPC (Nn / KSPLIT)       // 1024 keys per CTA
#define CHK 128                 // keys per chunk
#define NCHK (KPC / CHK)        // 8 chunks
#define BCN ((size_t)Bb * Cc * Nn)
#define LOG2E 1.4426950408889634f
#define SHIFT 10.0f             // p' = 2^(s-SHIFT); cancels in v = num/den

// Scratch
__device__ float d_f[Bb * Nn * 8];
__device__ float d_h[Bb * Nn * 8];
__device__ float d_g[Bb * Nn * 8];   // pre-scaled by log2e
__device__ float d_pacc[(size_t)KSPLIT * Bb * Nn * 8];
__device__ float d_pden[(size_t)KSPLIT * Bb * Nn];

// ---------------- helpers ----------------
__device__ __forceinline__ float ex2f(float x) {
    float y; asm("ex2.approx.f32 %0, %1;" : "=f"(y) : "f"(x)); return y;
}
// Dekker split of 2 floats into bf16 hi-pair word (lo16=a, hi16=b) and lo-pair word
__device__ __forceinline__ void pack_split(float a, float b, uint32_t& hw, uint32_t& lw) {
    uint32_t h;
    asm("cvt.rn.bf16x2.f32 %0, %1, %2;" : "=r"(h) : "f"(b), "f"(a));
    const float ah = __uint_as_float(h << 16);
    const float bh = __uint_as_float(h & 0xFFFF0000u);
    const float al = a - ah, bl = b - bh;
    uint32_t l;
    asm("cvt.rn.bf16x2.f32 %0, %1, %2;" : "=r"(l) : "f"(bl), "f"(al));
    hw = h; lw = l;
}
// fp16x2 pack with satfinite (no inf/NaN possible); lo16=a, hi16=b
__device__ __forceinline__ uint32_t pkf16s(float a, float b) {
    uint32_t r;
    asm("cvt.rn.satfinite.f16x2.f32 %0, %1, %2;" : "=r"(r) : "f"(b), "f"(a));
    return r;
}
// unpack fp16x2 word back to two f32 (for consistent denominator)
__device__ __forceinline__ float2 unpk16(uint32_t w) {
    float lo, hi;
    asm("{\n\t.reg .f16 l, h;\n\tmov.b32 {l, h}, %2;\n\t"
        "cvt.f32.f16 %0, l;\n\tcvt.f32.f16 %1, h;\n\t}"
        : "=f"(lo), "=f"(hi) : "r"(w));
    return make_float2(lo, hi);
}
// m16n8k16 bf16 MMA, row.col, f32 accumulate (D += A*B)
__device__ __forceinline__ void mma16816(float* d, const uint32_t* a,
                                         uint32_t b0, uint32_t b1) {
    asm volatile("mma.sync.aligned.m16n8k16.row.col.f32.bf16.bf16.f32 "
        "{%0,%1,%2,%3}, {%4,%5,%6,%7}, {%8,%9}, {%0,%1,%2,%3};"
        : "+f"(d[0]), "+f"(d[1]), "+f"(d[2]), "+f"(d[3])
        : "r"(a[0]), "r"(a[1]), "r"(a[2]), "r"(a[3]), "r"(b0), "r"(b1));
}
// m16n8k16 fp16 MMA, row.col, f32 accumulate
__device__ __forceinline__ void mma16816h(float* d, const uint32_t* a,
                                          uint32_t b0, uint32_t b1) {
    asm volatile("mma.sync.aligned.m16n8k16.row.col.f32.f16.f16.f32 "
        "{%0,%1,%2,%3}, {%4,%5,%6,%7}, {%8,%9}, {%0,%1,%2,%3};"
        : "+f"(d[0]), "+f"(d[1]), "+f"(d[2]), "+f"(d[3])
        : "r"(a[0]), "r"(a[1]), "r"(a[2]), "r"(a[3]), "r"(b0), "r"(b1));
}

// ---------------- Kernel A: projections f, g, h ---------------------------
__global__ __launch_bounds__(512) void proj_kernel(
    const float* __restrict__ x,
    const float* __restrict__ Wk, const float* __restrict__ bk,
    const float* __restrict__ Wq, const float* __restrict__ bq,
    const float* __restrict__ Wv, const float* __restrict__ bv)
{
    __shared__ float wks[512], wqs[512], wvs[512];
    __shared__ float red[3][24][128];
    const int t = threadIdx.x, px = t & 127, part = t >> 7;
    const int b = blockIdx.y;
    const int n = blockIdx.x * 128 + px;

    wks[t] = Wk[t];
    wqs[t] = Wq[t] * LOG2E;
    wvs[t] = Wv[t];
    __syncthreads();

    float f[8], g[8], h[8];
    #pragma unroll
    for (int e = 0; e < 8; e++) { f[e] = 0.f; g[e] = 0.f; h[e] = 0.f; }

    const float* xp = &x[(size_t)b * 64 * Nn + n];
    #pragma unroll
    for (int i = 0; i < 16; i++) {
        const int c = part * 16 + i;
        const float xv = xp[(size_t)c * Nn];
        #pragma unroll
        for (int e = 0; e < 8; e++) {
            f[e] = fmaf(wks[e * 64 + c], xv, f[e]);
            g[e] = fmaf(wqs[e * 64 + c], xv, g[e]);
            h[e] = fmaf(wvs[e * 64 + c], xv, h[e]);
        }
    }
    if (part > 0) {
        #pragma unroll
        for (int e = 0; e < 8; e++) {
            red[part - 1][e][px]      = f[e];
            red[part - 1][8 + e][px]  = g[e];
            red[part - 1][16 + e][px] = h[e];
        }
    }
    __syncthreads();
    if (part == 0) {
        #pragma unroll
        for (int e = 0; e < 8; e++) {
            f[e] += red[0][e][px]      + red[1][e][px]      + red[2][e][px]      + bk[e];
            g[e] += red[0][8 + e][px]  + red[1][8 + e][px]  + red[2][8 + e][px]  + bq[e] * LOG2E;
            h[e] += red[0][16 + e][px] + red[1][16 + e][px] + red[2][16 + e][px] + bv[e];
        }
        const size_t o = (size_t)(b * Nn + n) * 8;
        float4* fp = (float4*)&d_f[o];
        fp[0] = make_float4(f[0], f[1], f[2], f[3]);
        fp[1] = make_float4(f[4], f[5], f[6], f[7]);
        float4* hp = (float4*)&d_h[o];
        hp[0] = make_float4(h[0], h[1], h[2], h[3]);
        hp[1] = make_float4(h[4], h[5], h[6], h[7]);
        float4* gp = (float4*)&d_g[o];
        gp[0] = make_float4(g[0], g[1], g[2], g[3]);
        gp[1] = make_float4(g[4], g[5], g[6], g[7]);
    }
}

// ---------------- Kernel B: FA2-style HMMA attention ----------------------
// grid (KSPLIT, Nn/128, Bb), block 128 (4 warps, 32 queries each).
// S: bf16 Dekker (exact). V: fp16 single-MMA, satfinite, consistent den.
__global__ __launch_bounds__(128) void attn_kernel()
{
    __shared__ __align__(16) uint32_t s_fh[2][128 * 4];  // f_hi bf16x2: [key][4]
    __shared__ __align__(16) uint32_t s_fl[2][128 * 4];  // f_lo
    __shared__ __align__(16) uint32_t s_hT[2][8 * 68];   // H^T fp16x2: 8 emb-rows, 68 u32 stride

    const int t = threadIdx.x, wid = t >> 5, lane = t & 31;
    const int ks = blockIdx.x, qt = blockIdx.y, b = blockIdx.z;
    const int kbase = ks * KPC;
    const int r = lane >> 2, c2 = (lane & 3) * 2;

    // G A-fragments (once): A[16q x 16] = [g_hi(8) | g_lo(8)] bf16
    uint32_t aG[2][4];
    #pragma unroll
    for (int mt = 0; mt < 2; mt++) {
        #pragma unroll
        for (int hh = 0; hh < 2; hh++) {
            const int q = qt * 128 + wid * 32 + mt * 16 + r + hh * 8;
            const float2 gv = *(const float2*)&d_g[((size_t)b * Nn + q) * 8 + c2];
            uint32_t hw, lw;
            pack_split(gv.x, gv.y, hw, lw);
            aG[mt][hh]     = hw;
            aG[mt][2 + hh] = lw;
        }
    }

    float vacc[2][4] = {{0.f,0.f,0.f,0.f},{0.f,0.f,0.f,0.f}};
    float den[2][2]  = {{0.f,0.f},{0.f,0.f}};

    auto load_chunk = [&](int ch, int buf) {
        const size_t kg = (size_t)b * Nn + kbase + ch * CHK;
        {   // F: thread t <-> key t, bf16 Dekker split
            const float4* fp = (const float4*)&d_f[(kg + t) * 8];
            const float4 f0 = fp[0], f1 = fp[1];
            uint32_t h0,l0,h1,l1,h2,l2,h3,l3;
            pack_split(f0.x, f0.y, h0, l0);
            pack_split(f0.z, f0.w, h1, l1);
            pack_split(f1.x, f1.y, h2, l2);
            pack_split(f1.z, f1.w, h3, l3);
            *(uint4*)&s_fh[buf][t * 4] = make_uint4(h0, h1, h2, h3);
            *(uint4*)&s_fl[buf][t * 4] = make_uint4(l0, l1, l2, l3);
        }
        if (t < 64) {  // H: thread t <-> keys 2t,2t+1, fp16 transpose-store
            const float4* ha = (const float4*)&d_h[(kg + 2 * t) * 8];
            const float4* hb = (const float4*)&d_h[(kg + 2 * t + 1) * 8];
            const float4 a0 = ha[0], a1 = ha[1], b0 = hb[0], b1 = hb[1];
            const float av[8] = {a0.x,a0.y,a0.z,a0.w,a1.x,a1.y,a1.z,a1.w};
            const float bv[8] = {b0.x,b0.y,b0.z,b0.w,b1.x,b1.y,b1.z,b1.w};
            #pragma unroll
            for (int d = 0; d < 8; d++)
                s_hT[buf][d * 68 + t] = pkf16s(av[d], bv[d]);
        }
    };

    auto compute = [&](int buf) {
        #pragma unroll
        for (int g = 0; g < 8; g++) {          // 16-key groups
            #pragma unroll
            for (int mt = 0; mt < 2; mt++) {
                // S: two n8 tiles, exact via bf16 hi+lo
                float s[8] = {0.f,0.f,0.f,0.f,0.f,0.f,0.f,0.f};
                #pragma unroll
                for (int nt = 0; nt < 2; nt++) {
                    const int key = g * 16 + nt * 8 + r;
                    const uint32_t bh = s_fh[buf][key * 4 + (lane & 3)];
                    const uint32_t bl = s_fl[buf][key * 4 + (lane & 3)];
                    mma16816(&s[nt * 4], aG[mt], bh, bh);  // (gh+gl)*fh
                    mma16816(&s[nt * 4], aG[mt], bl, bl);  // (gh+gl)*fl
                }
                // shifted exp, pack to fp16 (satfinite)
                float p[8];
                #pragma unroll
                for (int j = 0; j < 8; j++) p[j] = ex2f(s[j] - SHIFT);
                uint32_t ap[4];
                ap[0] = pkf16s(p[0], p[1]);
                ap[1] = pkf16s(p[2], p[3]);
                ap[2] = pkf16s(p[4], p[5]);
                ap[3] = pkf16s(p[6], p[7]);
                // consistent denominator: sum the fp16-quantized weights
                const float2 u0 = unpk16(ap[0]), u1 = unpk16(ap[1]);
                const float2 u2 = unpk16(ap[2]), u3 = unpk16(ap[3]);
                den[mt][0] += (u0.x + u0.y) + (u2.x + u2.y);
                den[mt][1] += (u1.x + u1.y) + (u3.x + u3.y);
                // V: single fp16 MMA over 16 keys
                const int kw = g * 8 + (lane & 3);
                const uint32_t b0 = s_hT[buf][r * 68 + kw];
                const uint32_t b1 = s_hT[buf][r * 68 + kw + 4];
                mma16816h(vacc[mt], ap, b0, b1);
            }
        }
    };

    load_chunk(0, 0);
    __syncthreads();
    for (int ch = 0; ch < NCHK; ch++) {
        if (ch + 1 < NCHK) load_chunk(ch + 1, (ch + 1) & 1);  // LDGs overlap compute
        compute(ch & 1);
        __syncthreads();
    }

    // Epilogue: quad-reduce den, write partials
    const size_t base = ((size_t)ks * Bb + b) * Nn;
    #pragma unroll
    for (int mt = 0; mt < 2; mt++) {
        #pragma unroll
        for (int hh = 0; hh < 2; hh++) {
            float dsum = den[mt][hh];
            dsum += __shfl_xor_sync(0xffffffffu, dsum, 1);
            dsum += __shfl_xor_sync(0xffffffffu, dsum, 2);
            const int q = qt * 128 + wid * 32 + mt * 16 + r + hh * 8;
            *(float2*)&d_pacc[(base + q) * 8 + c2] =
                make_float2(vacc[mt][2 * hh], vacc[mt][2 * hh + 1]);
            if ((lane & 3) == 0) d_pden[base + q] = dsum;
        }
    }
}

// ---------------- Kernel C: combine splits, Wo projection, y ---------------
__global__ __launch_bounds__(256) void out_kernel(
    const float* __restrict__ x,
    const float* __restrict__ Wo, const float* __restrict__ bo,
    const float* __restrict__ gamma, float* __restrict__ out)
{
    __shared__ float vs[8 * 128];
    __shared__ float wos[512], bos[64];
    const int t = threadIdx.x, px = t & 127, half = t >> 7;
    const int b = blockIdx.y;
    const int m = blockIdx.x * 128 + px;

    for (int i = t; i < 512; i += 256) wos[i] = Wo[i];
    if (t < 64) bos[t] = bo[t];

    if (half == 0) {
        float acc[8] = {0, 0, 0, 0, 0, 0, 0, 0};
        float den = 0.0f;
        #pragma unroll
        for (int s = 0; s < KSPLIT; s++) {
            const size_t base = ((size_t)s * Bb + b) * Nn + m;
            const float4* pp = (const float4*)&d_pacc[base * 8];
            const float4 a0 = pp[0], a1 = pp[1];
            acc[0] += a0.x; acc[1] += a0.y; acc[2] += a0.z; acc[3] += a0.w;
            acc[4] += a1.x; acc[5] += a1.y; acc[6] += a1.z; acc[7] += a1.w;
            den += d_pden[base];
        }
        const float inv = 1.0f / den;
        #pragma unroll
        for (int e = 0; e < 8; e++) vs[e * 128 + px] = acc[e] * inv;
    }
    __syncthreads();

    const float gam = gamma[0];
    #pragma unroll 4
    for (int ci = 0; ci < 32; ci++) {
        const int c = half * 32 + ci;
        float o = bos[c];
        #pragma unroll
        for (int e = 0; e < 8; e++) o = fmaf(wos[c * 8 + e], vs[e * 128 + px], o);
        const size_t idx = ((size_t)b * 64 + c) * Nn + m;
        out[BCN + idx] = o;
        out[idx]       = fmaf(gam, o, x[idx]);
    }
    if (b == 0 && m == 0 && half == 0) out[2 * BCN] = gam;
}

// ---------------- Launch ----------------------------------------------------
extern "C" void kernel_launch(void* const* d_in, const int* in_sizes, int n_in,
                              void* d_out, int out_size)
{
    const float* x     = (const float*)d_in[0];
    const float* Wk    = (const float*)d_in[1];
    const float* bk    = (const float*)d_in[2];
    const float* Wq    = (const float*)d_in[3];
    const float* bq    = (const float*)d_in[4];
    const float* Wv    = (const float*)d_in[5];
    const float* bv    = (const float*)d_in[6];
    const float* Wo    = (const float*)d_in[7];
    const float* bo    = (const float*)d_in[8];
    const float* gamma = (const float*)d_in[9];
    float* out = (float*)d_out;

    proj_kernel<<<dim3(Nn / 128, Bb), 512>>>(x, Wk, bk, Wq, bq, Wv, bv);
    attn_kernel<<<dim3(KSPLIT, Nn / 128, Bb), 128>>>();
    out_kernel<<<dim3(Nn / 128, Bb), 256>>>(x, Wo, bo, gamma, out);
}

// round 9
// speedup vs baseline: 2.6193x; 1.1730x over previous
#include <cuda_runtime.h>
#include <cuda_bf16.h>
#include <cstdint>

// Problem constants
#define Bb 8
#define Cc 64
#define Nn 4096
#define KSPLIT 4
#define KPC (Nn / KSPLIT)       // 1024 keys per CTA
#define CHK 128                 // keys per chunk
#define NCHK (KPC / CHK)        // 8 chunks
#define BCN ((size_t)Bb * Cc * Nn)
#define LOG2E 1.4426950408889634f
#define SHIFT 10.0f             // p' = 2^(s-SHIFT); cancels in v = num/den

// Scratch
__device__ float d_f[Bb * Nn * 8];
__device__ float d_h[Bb * Nn * 8];
__device__ float d_g[Bb * Nn * 8];   // pre-scaled by log2e
__device__ float d_pacc[(size_t)KSPLIT * Bb * Nn * 8];
__device__ float d_pden[(size_t)KSPLIT * Bb * Nn];

// ---------------- helpers ----------------
__device__ __forceinline__ float ex2f(float x) {
    float y; asm("ex2.approx.f32 %0, %1;" : "=f"(y) : "f"(x)); return y;
}
// Dekker split of 2 floats into bf16 hi-pair word (lo16=a, hi16=b) and lo-pair word
__device__ __forceinline__ void pack_split(float a, float b, uint32_t& hw, uint32_t& lw) {
    uint32_t h;
    asm("cvt.rn.bf16x2.f32 %0, %1, %2;" : "=r"(h) : "f"(b), "f"(a));
    const float ah = __uint_as_float(h << 16);
    const float bh = __uint_as_float(h & 0xFFFF0000u);
    const float al = a - ah, bl = b - bh;
    uint32_t l;
    asm("cvt.rn.bf16x2.f32 %0, %1, %2;" : "=r"(l) : "f"(bl), "f"(al));
    hw = h; lw = l;
}
// fp16x2 pack with satfinite (no inf/NaN possible); lo16=a, hi16=b
__device__ __forceinline__ uint32_t pkf16s(float a, float b) {
    uint32_t r;
    asm("cvt.rn.satfinite.f16x2.f32 %0, %1, %2;" : "=r"(r) : "f"(b), "f"(a));
    return r;
}
// m16n8k16 bf16 MMA, row.col, f32 accumulate (D += A*B)
__device__ __forceinline__ void mma16816(float* d, const uint32_t* a,
                                         uint32_t b0, uint32_t b1) {
    asm volatile("mma.sync.aligned.m16n8k16.row.col.f32.bf16.bf16.f32 "
        "{%0,%1,%2,%3}, {%4,%5,%6,%7}, {%8,%9}, {%0,%1,%2,%3};"
        : "+f"(d[0]), "+f"(d[1]), "+f"(d[2]), "+f"(d[3])
        : "r"(a[0]), "r"(a[1]), "r"(a[2]), "r"(a[3]), "r"(b0), "r"(b1));
}
// m16n8k16 fp16 MMA, row.col, f32 accumulate
__device__ __forceinline__ void mma16816h(float* d, const uint32_t* a,
                                          uint32_t b0, uint32_t b1) {
    asm volatile("mma.sync.aligned.m16n8k16.row.col.f32.f16.f16.f32 "
        "{%0,%1,%2,%3}, {%4,%5,%6,%7}, {%8,%9}, {%0,%1,%2,%3};"
        : "+f"(d[0]), "+f"(d[1]), "+f"(d[2]), "+f"(d[3])
        : "r"(a[0]), "r"(a[1]), "r"(a[2]), "r"(a[3]), "r"(b0), "r"(b1));
}

// ---------------- Kernel A: projections f, g, h ---------------------------
// grid (Nn/128, Bb), block 256: 128 px x 2 channel-halves, smem combine.
__global__ __launch_bounds__(256) void proj_kernel(
    const float* __restrict__ x,
    const float* __restrict__ Wk, const float* __restrict__ bk,
    const float* __restrict__ Wq, const float* __restrict__ bq,
    const float* __restrict__ Wv, const float* __restrict__ bv)
{
    __shared__ float wks[512], wqs[512], wvs[512];
    __shared__ float red[24][128];      // part 1 stages its partials
    const int t = threadIdx.x, px = t & 127, part = t >> 7;
    const int b = blockIdx.y;
    const int n = blockIdx.x * 128 + px;

    for (int i = t; i < 512; i += 256) {
        wks[i] = Wk[i];
        wqs[i] = Wq[i] * LOG2E;
        wvs[i] = Wv[i];
    }
    __syncthreads();

    float f[8], g[8], h[8];
    #pragma unroll
    for (int e = 0; e < 8; e++) { f[e] = 0.f; g[e] = 0.f; h[e] = 0.f; }

    const float* xp = &x[(size_t)b * 64 * Nn + n];
    #pragma unroll 8
    for (int i = 0; i < 32; i++) {
        const int c = part * 32 + i;
        const float xv = xp[(size_t)c * Nn];
        #pragma unroll
        for (int e = 0; e < 8; e++) {
            f[e] = fmaf(wks[e * 64 + c], xv, f[e]);
            g[e] = fmaf(wqs[e * 64 + c], xv, g[e]);
            h[e] = fmaf(wvs[e * 64 + c], xv, h[e]);
        }
    }
    if (part == 1) {
        #pragma unroll
        for (int e = 0; e < 8; e++) {
            red[e][px]      = f[e];
            red[8 + e][px]  = g[e];
            red[16 + e][px] = h[e];
        }
    }
    __syncthreads();
    if (part == 0) {
        #pragma unroll
        for (int e = 0; e < 8; e++) {
            f[e] += red[e][px]      + bk[e];
            g[e] += red[8 + e][px]  + bq[e] * LOG2E;
            h[e] += red[16 + e][px] + bv[e];
        }
        const size_t o = (size_t)(b * Nn + n) * 8;
        float4* fp = (float4*)&d_f[o];
        fp[0] = make_float4(f[0], f[1], f[2], f[3]);
        fp[1] = make_float4(f[4], f[5], f[6], f[7]);
        float4* hp = (float4*)&d_h[o];
        hp[0] = make_float4(h[0], h[1], h[2], h[3]);
        hp[1] = make_float4(h[4], h[5], h[6], h[7]);
        float4* gp = (float4*)&d_g[o];
        gp[0] = make_float4(g[0], g[1], g[2], g[3]);
        gp[1] = make_float4(g[4], g[5], g[6], g[7]);
    }
}

// ---------------- Kernel B: FA2-style HMMA attention ----------------------
// grid (KSPLIT, Nn/128, Bb), block 128 (4 warps, 32 queries each).
// S: bf16 Dekker (exact), accumulator pre-biased with -SHIFT.
// V: fp16 single-MMA, satfinite. den: f32 sums of p.
__global__ __launch_bounds__(128) void attn_kernel()
{
    __shared__ __align__(16) uint32_t s_fh[2][128 * 4];  // f_hi bf16x2: [key][4]
    __shared__ __align__(16) uint32_t s_fl[2][128 * 4];  // f_lo
    __shared__ __align__(16) uint32_t s_hT[2][8 * 68];   // H^T fp16x2: 8 emb-rows, 68 u32 stride

    const int t = threadIdx.x, wid = t >> 5, lane = t & 31;
    const int ks = blockIdx.x, qt = blockIdx.y, b = blockIdx.z;
    const int kbase = ks * KPC;
    const int r = lane >> 2, c2 = (lane & 3) * 2;

    // G A-fragments (once): A[16q x 16] = [g_hi(8) | g_lo(8)] bf16
    uint32_t aG[2][4];
    #pragma unroll
    for (int mt = 0; mt < 2; mt++) {
        #pragma unroll
        for (int hh = 0; hh < 2; hh++) {
            const int q = qt * 128 + wid * 32 + mt * 16 + r + hh * 8;
            const float2 gv = *(const float2*)&d_g[((size_t)b * Nn + q) * 8 + c2];
            uint32_t hw, lw;
            pack_split(gv.x, gv.y, hw, lw);
            aG[mt][hh]     = hw;
            aG[mt][2 + hh] = lw;
        }
    }

    float vacc[2][4] = {{0.f,0.f,0.f,0.f},{0.f,0.f,0.f,0.f}};
    float den[2][2]  = {{0.f,0.f},{0.f,0.f}};

    auto load_chunk = [&](int ch, int buf) {
        const size_t kg = (size_t)b * Nn + kbase + ch * CHK;
        {   // F: thread t <-> key t, bf16 Dekker split
            const float4* fp = (const float4*)&d_f[(kg + t) * 8];
            const float4 f0 = fp[0], f1 = fp[1];
            uint32_t h0,l0,h1,l1,h2,l2,h3,l3;
            pack_split(f0.x, f0.y, h0, l0);
            pack_split(f0.z, f0.w, h1, l1);
            pack_split(f1.x, f1.y, h2, l2);
            pack_split(f1.z, f1.w, h3, l3);
            *(uint4*)&s_fh[buf][t * 4] = make_uint4(h0, h1, h2, h3);
            *(uint4*)&s_fl[buf][t * 4] = make_uint4(l0, l1, l2, l3);
        }
        if (t < 64) {  // H: thread t <-> keys 2t,2t+1, fp16 transpose-store
            const float4* ha = (const float4*)&d_h[(kg + 2 * t) * 8];
            const float4* hb = (const float4*)&d_h[(kg + 2 * t + 1) * 8];
            const float4 a0 = ha[0], a1 = ha[1], b0 = hb[0], b1 = hb[1];
            const float av[8] = {a0.x,a0.y,a0.z,a0.w,a1.x,a1.y,a1.z,a1.w};
            const float bv[8] = {b0.x,b0.y,b0.z,b0.w,b1.x,b1.y,b1.z,b1.w};
            #pragma unroll
            for (int d = 0; d < 8; d++)
                s_hT[buf][d * 68 + t] = pkf16s(av[d], bv[d]);
        }
    };

    auto compute = [&](int buf) {
        #pragma unroll
        for (int g = 0; g < 8; g++) {          // 16-key groups
            #pragma unroll
            for (int mt = 0; mt < 2; mt++) {
                // S: two n8 tiles, exact via bf16 hi+lo; acc pre-biased -SHIFT
                float s[8] = {-SHIFT,-SHIFT,-SHIFT,-SHIFT,-SHIFT,-SHIFT,-SHIFT,-SHIFT};
                #pragma unroll
                for (int nt = 0; nt < 2; nt++) {
                    const int key = g * 16 + nt * 8 + r;
                    const uint32_t bh = s_fh[buf][key * 4 + (lane & 3)];
                    const uint32_t bl = s_fl[buf][key * 4 + (lane & 3)];
                    mma16816(&s[nt * 4], aG[mt], bh, bh);  // (gh+gl)*fh
                    mma16816(&s[nt * 4], aG[mt], bl, bl);  // (gh+gl)*fl
                }
                // p = 2^(s) (shift already applied via accumulator bias)
                float p[8];
                #pragma unroll
                for (int j = 0; j < 8; j++) p[j] = ex2f(s[j]);
                den[mt][0] += (p[0] + p[1]) + (p[4] + p[5]);
                den[mt][1] += (p[2] + p[3]) + (p[6] + p[7]);
                // P A-fragment, fp16 satfinite
                uint32_t ap[4];
                ap[0] = pkf16s(p[0], p[1]);
                ap[1] = pkf16s(p[2], p[3]);
                ap[2] = pkf16s(p[4], p[5]);
                ap[3] = pkf16s(p[6], p[7]);
                // V: single fp16 MMA over 16 keys
                const int kw = g * 8 + (lane & 3);
                const uint32_t b0 = s_hT[buf][r * 68 + kw];
                const uint32_t b1 = s_hT[buf][r * 68 + kw + 4];
                mma16816h(vacc[mt], ap, b0, b1);
            }
        }
    };

    load_chunk(0, 0);
    __syncthreads();
    for (int ch = 0; ch < NCHK; ch++) {
        if (ch + 1 < NCHK) load_chunk(ch + 1, (ch + 1) & 1);  // LDGs overlap compute
        compute(ch & 1);
        __syncthreads();
    }

    // Epilogue: quad-reduce den, write partials
    const size_t base = ((size_t)ks * Bb + b) * Nn;
    #pragma unroll
    for (int mt = 0; mt < 2; mt++) {
        #pragma unroll
        for (int hh = 0; hh < 2; hh++) {
            float dsum = den[mt][hh];
            dsum += __shfl_xor_sync(0xffffffffu, dsum, 1);
            dsum += __shfl_xor_sync(0xffffffffu, dsum, 2);
            const int q = qt * 128 + wid * 32 + mt * 16 + r + hh * 8;
            *(float2*)&d_pacc[(base + q) * 8 + c2] =
                make_float2(vacc[mt][2 * hh], vacc[mt][2 * hh + 1]);
            if ((lane & 3) == 0) d_pden[base + q] = dsum;
        }
    }
}

// ---------------- Kernel C: combine splits, Wo projection, y ---------------
__global__ __launch_bounds__(256) void out_kernel(
    const float* __restrict__ x,
    const float* __restrict__ Wo, const float* __restrict__ bo,
    const float* __restrict__ gamma, float* __restrict__ out)
{
    __shared__ float vs[8 * 128];
    __shared__ float wos[512], bos[64];
    const int t = threadIdx.x, px = t & 127, half = t >> 7;
    const int b = blockIdx.y;
    const int m = blockIdx.x * 128 + px;

    for (int i = t; i < 512; i += 256) wos[i] = Wo[i];
    if (t < 64) bos[t] = bo[t];

    if (half == 0) {
        float acc[8] = {0, 0, 0, 0, 0, 0, 0, 0};
        float den = 0.0f;
        #pragma unroll
        for (int s = 0; s < KSPLIT; s++) {
            const size_t base = ((size_t)s * Bb + b) * Nn + m;
            const float4* pp = (const float4*)&d_pacc[base * 8];
            const float4 a0 = pp[0], a1 = pp[1];
            acc[0] += a0.x; acc[1] += a0.y; acc[2] += a0.z; acc[3] += a0.w;
            acc[4] += a1.x; acc[5] += a1.y; acc[6] += a1.z; acc[7] += a1.w;
            den += d_pden[base];
        }
        const float inv = 1.0f / den;
        #pragma unroll
        for (int e = 0; e < 8; e++) vs[e * 128 + px] = acc[e] * inv;
    }
    __syncthreads();

    const float gam = gamma[0];
    #pragma unroll 4
    for (int ci = 0; ci < 32; ci++) {
        const int c = half * 32 + ci;
        float o = bos[c];
        #pragma unroll
        for (int e = 0; e < 8; e++) o = fmaf(wos[c * 8 + e], vs[e * 128 + px], o);
        const size_t idx = ((size_t)b * 64 + c) * Nn + m;
        out[BCN + idx] = o;
        out[idx]       = fmaf(gam, o, x[idx]);
    }
    if (b == 0 && m == 0 && half == 0) out[2 * BCN] = gam;
}

// ---------------- Launch ----------------------------------------------------
extern "C" void kernel_launch(void* const* d_in, const int* in_sizes, int n_in,
                              void* d_out, int out_size)
{
    const float* x     = (const float*)d_in[0];
    const float* Wk    = (const float*)d_in[1];
    const float* bk    = (const float*)d_in[2];
    const float* Wq    = (const float*)d_in[3];
    const float* bq    = (const float*)d_in[4];
    const float* Wv    = (const float*)d_in[5];
    const float* bv    = (const float*)d_in[6];
    const float* Wo    = (const float*)d_in[7];
    const float* bo    = (const float*)d_in[8];
    const float* gamma = (const float*)d_in[9];
    float* out = (float*)d_out;

    proj_kernel<<<dim3(Nn / 128, Bb), 256>>>(x, Wk, bk, Wq, bq, Wv, bv);
    attn_kernel<<<dim3(KSPLIT, Nn / 128, Bb), 128>>>();
    out_kernel<<<dim3(Nn / 128, Bb), 256>>>(x, Wo, bo, gamma, out);
}

// round 10
// speedup vs baseline: 2.6583x; 1.0149x over previous
#include <cuda_runtime.h>
#include <cuda_bf16.h>
#include <cstdint>

// Problem constants
#define Bb 8
#define Cc 64
#define Nn 4096
#define KSPLIT 4
#define KPC (Nn / KSPLIT)       // 1024 keys per CTA
#define CHK 256                 // keys per chunk
#define NCHK (KPC / CHK)        // 4 chunks
#define BCN ((size_t)Bb * Cc * Nn)
#define LOG2E 1.4426950408889634f
#define SHIFT 10.0f             // p' = 2^(s-SHIFT); cancels in v = num/den

// Scratch
__device__ float d_f[Bb * Nn * 8];
__device__ float d_h[Bb * Nn * 8];
__device__ float d_g[Bb * Nn * 8];   // pre-scaled by log2e
__device__ float d_pacc[(size_t)KSPLIT * Bb * Nn * 8];
__device__ float d_pden[(size_t)KSPLIT * Bb * Nn];

// ---------------- helpers ----------------
__device__ __forceinline__ float ex2f(float x) {
    float y; asm("ex2.approx.f32 %0, %1;" : "=f"(y) : "f"(x)); return y;
}
// Dekker split of 2 floats into bf16 hi-pair word (lo16=a, hi16=b) and lo-pair word
__device__ __forceinline__ void pack_split(float a, float b, uint32_t& hw, uint32_t& lw) {
    uint32_t h;
    asm("cvt.rn.bf16x2.f32 %0, %1, %2;" : "=r"(h) : "f"(b), "f"(a));
    const float ah = __uint_as_float(h << 16);
    const float bh = __uint_as_float(h & 0xFFFF0000u);
    const float al = a - ah, bl = b - bh;
    uint32_t l;
    asm("cvt.rn.bf16x2.f32 %0, %1, %2;" : "=r"(l) : "f"(bl), "f"(al));
    hw = h; lw = l;
}
// fp16x2 pack with satfinite (no inf/NaN possible); lo16=a, hi16=b
__device__ __forceinline__ uint32_t pkf16s(float a, float b) {
    uint32_t r;
    asm("cvt.rn.satfinite.f16x2.f32 %0, %1, %2;" : "=r"(r) : "f"(b), "f"(a));
    return r;
}
// m16n8k16 bf16 MMA, row.col, f32 accumulate (D += A*B)
__device__ __forceinline__ void mma16816(float* d, const uint32_t* a,
                                         uint32_t b0, uint32_t b1) {
    asm volatile("mma.sync.aligned.m16n8k16.row.col.f32.bf16.bf16.f32 "
        "{%0,%1,%2,%3}, {%4,%5,%6,%7}, {%8,%9}, {%0,%1,%2,%3};"
        : "+f"(d[0]), "+f"(d[1]), "+f"(d[2]), "+f"(d[3])
        : "r"(a[0]), "r"(a[1]), "r"(a[2]), "r"(a[3]), "r"(b0), "r"(b1));
}
// m16n8k16 fp16 MMA, row.col, f32 accumulate
__device__ __forceinline__ void mma16816h(float* d, const uint32_t* a,
                                          uint32_t b0, uint32_t b1) {
    asm volatile("mma.sync.aligned.m16n8k16.row.col.f32.f16.f16.f32 "
        "{%0,%1,%2,%3}, {%4,%5,%6,%7}, {%8,%9}, {%0,%1,%2,%3};"
        : "+f"(d[0]), "+f"(d[1]), "+f"(d[2]), "+f"(d[3])
        : "r"(a[0]), "r"(a[1]), "r"(a[2]), "r"(a[3]), "r"(b0), "r"(b1));
}

// ---------------- Kernel A: projections f, g, h ---------------------------
// grid (Nn/128, Bb), block 256: 128 px x 2 channel-halves, smem combine.
// x values front-loaded into registers for max MLP.
__global__ __launch_bounds__(256) void proj_kernel(
    const float* __restrict__ x,
    const float* __restrict__ Wk, const float* __restrict__ bk,
    const float* __restrict__ Wq, const float* __restrict__ bq,
    const float* __restrict__ Wv, const float* __restrict__ bv)
{
    __shared__ float wks[512], wqs[512], wvs[512];
    __shared__ float red[24][128];      // part 1 stages its partials
    const int t = threadIdx.x, px = t & 127, part = t >> 7;
    const int b = blockIdx.y;
    const int n = blockIdx.x * 128 + px;

    // front-load x (32 independent LDGs)
    float xv[32];
    const float* xp = &x[((size_t)b * 64 + part * 32) * Nn + n];
    #pragma unroll
    for (int i = 0; i < 32; i++) xv[i] = xp[(size_t)i * Nn];

    for (int i = t; i < 512; i += 256) {
        wks[i] = Wk[i];
        wqs[i] = Wq[i] * LOG2E;
        wvs[i] = Wv[i];
    }
    __syncthreads();

    float f[8], g[8], h[8];
    #pragma unroll
    for (int e = 0; e < 8; e++) { f[e] = 0.f; g[e] = 0.f; h[e] = 0.f; }

    #pragma unroll
    for (int i = 0; i < 32; i++) {
        const int c = part * 32 + i;
        #pragma unroll
        for (int e = 0; e < 8; e++) {
            f[e] = fmaf(wks[e * 64 + c], xv[i], f[e]);
            g[e] = fmaf(wqs[e * 64 + c], xv[i], g[e]);
            h[e] = fmaf(wvs[e * 64 + c], xv[i], h[e]);
        }
    }
    if (part == 1) {
        #pragma unroll
        for (int e = 0; e < 8; e++) {
            red[e][px]      = f[e];
            red[8 + e][px]  = g[e];
            red[16 + e][px] = h[e];
        }
    }
    __syncthreads();
    if (part == 0) {
        #pragma unroll
        for (int e = 0; e < 8; e++) {
            f[e] += red[e][px]      + bk[e];
            g[e] += red[8 + e][px]  + bq[e] * LOG2E;
            h[e] += red[16 + e][px] + bv[e];
        }
        const size_t o = (size_t)(b * Nn + n) * 8;
        float4* fp = (float4*)&d_f[o];
        fp[0] = make_float4(f[0], f[1], f[2], f[3]);
        fp[1] = make_float4(f[4], f[5], f[6], f[7]);
        float4* hp = (float4*)&d_h[o];
        hp[0] = make_float4(h[0], h[1], h[2], h[3]);
        hp[1] = make_float4(h[4], h[5], h[6], h[7]);
        float4* gp = (float4*)&d_g[o];
        gp[0] = make_float4(g[0], g[1], g[2], g[3]);
        gp[1] = make_float4(g[4], g[5], g[6], g[7]);
    }
}

// ---------------- Kernel B: FA2-style HMMA attention ----------------------
// grid (KSPLIT, Nn/128, Bb), block 128 (4 warps, 32 queries each).
// S: bf16 Dekker (exact), accumulator pre-biased with -SHIFT.
// V: fp16 single-MMA, satfinite. den: extra fp16 MMA with ones-B.
__global__ __launch_bounds__(128) void attn_kernel()
{
    __shared__ __align__(16) uint32_t s_fh[2][CHK * 4];   // f_hi bf16x2: [key][4]
    __shared__ __align__(16) uint32_t s_fl[2][CHK * 4];   // f_lo
    __shared__ __align__(16) uint32_t s_hT[2][8 * 132];   // H^T fp16x2: 8 emb-rows, 132 u32 stride

    const int t = threadIdx.x, wid = t >> 5, lane = t & 31;
    const int ks = blockIdx.x, qt = blockIdx.y, b = blockIdx.z;
    const int kbase = ks * KPC;
    const int r = lane >> 2, c2 = (lane & 3) * 2;
    const uint32_t ONES = 0x3C003C00u;   // fp16x2 {1,1}

    // G A-fragments (once): A[16q x 16] = [g_hi(8) | g_lo(8)] bf16
    uint32_t aG[2][4];
    #pragma unroll
    for (int mt = 0; mt < 2; mt++) {
        #pragma unroll
        for (int hh = 0; hh < 2; hh++) {
            const int q = qt * 128 + wid * 32 + mt * 16 + r + hh * 8;
            const float2 gv = *(const float2*)&d_g[((size_t)b * Nn + q) * 8 + c2];
            uint32_t hw, lw;
            pack_split(gv.x, gv.y, hw, lw);
            aG[mt][hh]     = hw;
            aG[mt][2 + hh] = lw;
        }
    }

    float vacc[2][4] = {{0.f,0.f,0.f,0.f},{0.f,0.f,0.f,0.f}};
    float dacc[2][4] = {{0.f,0.f,0.f,0.f},{0.f,0.f,0.f,0.f}};

    auto load_chunk = [&](int ch, int buf) {
        const size_t kg = (size_t)b * Nn + kbase + ch * CHK;
        // F: keys t and t+128, bf16 Dekker split
        #pragma unroll
        for (int kk = 0; kk < 2; kk++) {
            const int key = t + kk * 128;
            const float4* fp = (const float4*)&d_f[(kg + key) * 8];
            const float4 f0 = fp[0], f1 = fp[1];
            uint32_t h0,l0,h1,l1,h2,l2,h3,l3;
            pack_split(f0.x, f0.y, h0, l0);
            pack_split(f0.z, f0.w, h1, l1);
            pack_split(f1.x, f1.y, h2, l2);
            pack_split(f1.z, f1.w, h3, l3);
            *(uint4*)&s_fh[buf][key * 4] = make_uint4(h0, h1, h2, h3);
            *(uint4*)&s_fl[buf][key * 4] = make_uint4(l0, l1, l2, l3);
        }
        // H: keys 2t, 2t+1, fp16 transpose-store (all 128 threads)
        {
            const float4* ha = (const float4*)&d_h[(kg + 2 * t) * 8];
            const float4* hb = (const float4*)&d_h[(kg + 2 * t + 1) * 8];
            const float4 a0 = ha[0], a1 = ha[1], b0 = hb[0], b1 = hb[1];
            const float av[8] = {a0.x,a0.y,a0.z,a0.w,a1.x,a1.y,a1.z,a1.w};
            const float bv[8] = {b0.x,b0.y,b0.z,b0.w,b1.x,b1.y,b1.z,b1.w};
            #pragma unroll
            for (int d = 0; d < 8; d++)
                s_hT[buf][d * 132 + t] = pkf16s(av[d], bv[d]);
        }
    };

    auto compute = [&](int buf) {
        #pragma unroll
        for (int g = 0; g < 16; g++) {         // 16-key groups
            #pragma unroll
            for (int mt = 0; mt < 2; mt++) {
                // S: two n8 tiles, exact via bf16 hi+lo; acc pre-biased -SHIFT
                float s[8] = {-SHIFT,-SHIFT,-SHIFT,-SHIFT,-SHIFT,-SHIFT,-SHIFT,-SHIFT};
                #pragma unroll
                for (int nt = 0; nt < 2; nt++) {
                    const int key = g * 16 + nt * 8 + r;
                    const uint32_t bh = s_fh[buf][key * 4 + (lane & 3)];
                    const uint32_t bl = s_fl[buf][key * 4 + (lane & 3)];
                    mma16816(&s[nt * 4], aG[mt], bh, bh);  // (gh+gl)*fh
                    mma16816(&s[nt * 4], aG[mt], bl, bl);  // (gh+gl)*fl
                }
                // p = 2^s (shift folded into accumulator bias)
                float p[8];
                #pragma unroll
                for (int j = 0; j < 8; j++) p[j] = ex2f(s[j]);
                // P A-fragment, fp16 satfinite
                uint32_t ap[4];
                ap[0] = pkf16s(p[0], p[1]);
                ap[1] = pkf16s(p[2], p[3]);
                ap[2] = pkf16s(p[4], p[5]);
                ap[3] = pkf16s(p[6], p[7]);
                // V: single fp16 MMA over 16 keys
                const int kw = g * 8 + (lane & 3);
                const uint32_t b0 = s_hT[buf][r * 132 + kw];
                const uint32_t b1 = s_hT[buf][r * 132 + kw + 4];
                mma16816h(vacc[mt], ap, b0, b1);
                // den: P row-sum via ones-B MMA (tensor pipe)
                mma16816h(dacc[mt], ap, ONES, ONES);
            }
        }
    };

    load_chunk(0, 0);
    __syncthreads();
    for (int ch = 0; ch < NCHK; ch++) {
        if (ch + 1 < NCHK) load_chunk(ch + 1, (ch + 1) & 1);  // LDGs overlap compute
        compute(ch & 1);
        __syncthreads();
    }

    // Epilogue: dacc already holds full row-sums (all cols identical)
    const size_t base = ((size_t)ks * Bb + b) * Nn;
    #pragma unroll
    for (int mt = 0; mt < 2; mt++) {
        #pragma unroll
        for (int hh = 0; hh < 2; hh++) {
            const int q = qt * 128 + wid * 32 + mt * 16 + r + hh * 8;
            *(float2*)&d_pacc[(base + q) * 8 + c2] =
                make_float2(vacc[mt][2 * hh], vacc[mt][2 * hh + 1]);
            if ((lane & 3) == 0) d_pden[base + q] = dacc[mt][2 * hh];
        }
    }
}

// ---------------- Kernel C: combine splits, Wo projection, y ---------------
__global__ __launch_bounds__(256) void out_kernel(
    const float* __restrict__ x,
    const float* __restrict__ Wo, const float* __restrict__ bo,
    const float* __restrict__ gamma, float* __restrict__ out)
{
    __shared__ float vs[8 * 128];
    __shared__ float wos[512], bos[64];
    const int t = threadIdx.x, px = t & 127, half = t >> 7;
    const int b = blockIdx.y;
    const int m = blockIdx.x * 128 + px;

    for (int i = t; i < 512; i += 256) wos[i] = Wo[i];
    if (t < 64) bos[t] = bo[t];

    if (half == 0) {
        float acc[8] = {0, 0, 0, 0, 0, 0, 0, 0};
        float den = 0.0f;
        #pragma unroll
        for (int s = 0; s < KSPLIT; s++) {
            const size_t base = ((size_t)s * Bb + b) * Nn + m;
            const float4* pp = (const float4*)&d_pacc[base * 8];
            const float4 a0 = pp[0], a1 = pp[1];
            acc[0] += a0.x; acc[1] += a0.y; acc[2] += a0.z; acc[3] += a0.w;
            acc[4] += a1.x; acc[5] += a1.y; acc[6] += a1.z; acc[7] += a1.w;
            den += d_pden[base];
        }
        const float inv = 1.0f / den;
        #pragma unroll
        for (int e = 0; e < 8; e++) vs[e * 128 + px] = acc[e] * inv;
    }
    __syncthreads();

    const float gam = gamma[0];
    #pragma unroll 4
    for (int ci = 0; ci < 32; ci++) {
        const int c = half * 32 + ci;
        float o = bos[c];
        #pragma unroll
        for (int e = 0; e < 8; e++) o = fmaf(wos[c * 8 + e], vs[e * 128 + px], o);
        const size_t idx = ((size_t)b * 64 + c) * Nn + m;
        out[BCN + idx] = o;
        out[idx]       = fmaf(gam, o, x[idx]);
    }
    if (b == 0 && m == 0 && half == 0) out[2 * BCN] = gam;
}

// ---------------- Launch ----------------------------------------------------
extern "C" void kernel_launch(void* const* d_in, const int* in_sizes, int n_in,
                              void* d_out, int out_size)
{
    const float* x     = (const float*)d_in[0];
    const float* Wk    = (const float*)d_in[1];
    const float* bk    = (const float*)d_in[2];
    const float* Wq    = (const float*)d_in[3];
    const float* bq    = (const float*)d_in[4];
    const float* Wv    = (const float*)d_in[5];
    const float* bv    = (const float*)d_in[6];
    const float* Wo    = (const float*)d_in[7];
    const float* bo    = (const float*)d_in[8];
    const float* gamma = (const float*)d_in[9];
    float* out = (float*)d_out;

    proj_kernel<<<dim3(Nn / 128, Bb), 256>>>(x, Wk, bk, Wq, bq, Wv, bv);
    attn_kernel<<<dim3(KSPLIT, Nn / 128, Bb), 128>>>();
    out_kernel<<<dim3(Nn / 128, Bb), 256>>>(x, Wo, bo, gamma, out);
}

// round 11
// speedup vs baseline: 2.9007x; 1.0912x over previous
#include <cuda_runtime.h>
#include <cuda_bf16.h>
#include <cstdint>

// Problem constants
#define Bb 8
#define Cc 64
#define Nn 4096
#define BN (Bb * Nn)
#define KSPLIT 4
#define KPC (Nn / KSPLIT)       // 1024 keys per CTA
#define CHK 256                 // keys per chunk
#define NCHK (KPC / CHK)        // 4 chunks
#define BCN ((size_t)Bb * Cc * Nn)
#define LOG2E 1.4426950408889634f
#define SHIFT 10.0f             // p' = 2^(s-SHIFT); cancels in v = num/den

// Scratch
__device__ uint32_t d_fpk[(size_t)BN * 8];        // per key: fh0..3, fl0..3 (bf16x2)
__device__ unsigned short d_hT[8 * (size_t)BN];   // fp16, [emb][b*Nn + n]
__device__ float d_g[(size_t)BN * 8];             // pre-scaled by log2e
__device__ float d_pacc[(size_t)KSPLIT * BN * 8];
__device__ float d_pden[(size_t)KSPLIT * BN];

// ---------------- helpers ----------------
__device__ __forceinline__ float ex2f(float x) {
    float y; asm("ex2.approx.f32 %0, %1;" : "=f"(y) : "f"(x)); return y;
}
// Dekker split of 2 floats into bf16 hi-pair word (lo16=a, hi16=b) and lo-pair word
__device__ __forceinline__ void pack_split(float a, float b, uint32_t& hw, uint32_t& lw) {
    uint32_t h;
    asm("cvt.rn.bf16x2.f32 %0, %1, %2;" : "=r"(h) : "f"(b), "f"(a));
    const float ah = __uint_as_float(h << 16);
    const float bh = __uint_as_float(h & 0xFFFF0000u);
    const float al = a - ah, bl = b - bh;
    uint32_t l;
    asm("cvt.rn.bf16x2.f32 %0, %1, %2;" : "=r"(l) : "f"(bl), "f"(al));
    hw = h; lw = l;
}
// fp16x2 pack with satfinite; lo16=a, hi16=b
__device__ __forceinline__ uint32_t pkf16s(float a, float b) {
    uint32_t r;
    asm("cvt.rn.satfinite.f16x2.f32 %0, %1, %2;" : "=r"(r) : "f"(b), "f"(a));
    return r;
}
__device__ __forceinline__ unsigned short f2h(float a) {
    unsigned short r;
    asm("cvt.rn.f16.f32 %0, %1;" : "=h"(r) : "f"(a));
    return r;
}
// m16n8k16 bf16 MMA, row.col, f32 accumulate (D += A*B)
__device__ __forceinline__ void mma16816(float* d, const uint32_t* a,
                                         uint32_t b0, uint32_t b1) {
    asm volatile("mma.sync.aligned.m16n8k16.row.col.f32.bf16.bf16.f32 "
        "{%0,%1,%2,%3}, {%4,%5,%6,%7}, {%8,%9}, {%0,%1,%2,%3};"
        : "+f"(d[0]), "+f"(d[1]), "+f"(d[2]), "+f"(d[3])
        : "r"(a[0]), "r"(a[1]), "r"(a[2]), "r"(a[3]), "r"(b0), "r"(b1));
}
// m16n8k16 fp16 MMA, row.col, f32 accumulate
__device__ __forceinline__ void mma16816h(float* d, const uint32_t* a,
                                          uint32_t b0, uint32_t b1) {
    asm volatile("mma.sync.aligned.m16n8k16.row.col.f32.f16.f16.f32 "
        "{%0,%1,%2,%3}, {%4,%5,%6,%7}, {%8,%9}, {%0,%1,%2,%3};"
        : "+f"(d[0]), "+f"(d[1]), "+f"(d[2]), "+f"(d[3])
        : "r"(a[0]), "r"(a[1]), "r"(a[2]), "r"(a[3]), "r"(b0), "r"(b1));
}

// ---------------- Kernel A: projections f, g, h (pre-packed outputs) ------
// grid (Nn/128, Bb), block 256: 128 px x 2 channel-halves, smem combine.
__global__ __launch_bounds__(256) void proj_kernel(
    const float* __restrict__ x,
    const float* __restrict__ Wk, const float* __restrict__ bk,
    const float* __restrict__ Wq, const float* __restrict__ bq,
    const float* __restrict__ Wv, const float* __restrict__ bv)
{
    __shared__ float wks[512], wqs[512], wvs[512];
    __shared__ float red[24][128];      // part 1 stages its partials
    const int t = threadIdx.x, px = t & 127, part = t >> 7;
    const int b = blockIdx.y;
    const int n = blockIdx.x * 128 + px;

    // front-load x (32 independent LDGs)
    float xv[32];
    const float* xp = &x[((size_t)b * 64 + part * 32) * Nn + n];
    #pragma unroll
    for (int i = 0; i < 32; i++) xv[i] = xp[(size_t)i * Nn];

    for (int i = t; i < 512; i += 256) {
        wks[i] = Wk[i];
        wqs[i] = Wq[i] * LOG2E;
        wvs[i] = Wv[i];
    }
    __syncthreads();

    float f[8], g[8], h[8];
    #pragma unroll
    for (int e = 0; e < 8; e++) { f[e] = 0.f; g[e] = 0.f; h[e] = 0.f; }

    #pragma unroll
    for (int i = 0; i < 32; i++) {
        const int c = part * 32 + i;
        #pragma unroll
        for (int e = 0; e < 8; e++) {
            f[e] = fmaf(wks[e * 64 + c], xv[i], f[e]);
            g[e] = fmaf(wqs[e * 64 + c], xv[i], g[e]);
            h[e] = fmaf(wvs[e * 64 + c], xv[i], h[e]);
        }
    }
    if (part == 1) {
        #pragma unroll
        for (int e = 0; e < 8; e++) {
            red[e][px]      = f[e];
            red[8 + e][px]  = g[e];
            red[16 + e][px] = h[e];
        }
    }
    __syncthreads();
    if (part == 0) {
        #pragma unroll
        for (int e = 0; e < 8; e++) {
            f[e] += red[e][px]      + bk[e];
            g[e] += red[8 + e][px]  + bq[e] * LOG2E;
            h[e] += red[16 + e][px] + bv[e];
        }
        const size_t bn = (size_t)b * Nn + n;
        // F: bf16 Dekker pre-pack
        uint32_t h0,l0,h1,l1,h2,l2,h3,l3;
        pack_split(f[0], f[1], h0, l0);
        pack_split(f[2], f[3], h1, l1);
        pack_split(f[4], f[5], h2, l2);
        pack_split(f[6], f[7], h3, l3);
        uint4* fp = (uint4*)&d_fpk[bn * 8];
        fp[0] = make_uint4(h0, h1, h2, h3);
        fp[1] = make_uint4(l0, l1, l2, l3);
        // H: fp16 transposed
        #pragma unroll
        for (int e = 0; e < 8; e++)
            d_hT[(size_t)e * BN + bn] = f2h(h[e]);
        // G: f32
        float4* gp = (float4*)&d_g[bn * 8];
        gp[0] = make_float4(g[0], g[1], g[2], g[3]);
        gp[1] = make_float4(g[4], g[5], g[6], g[7]);
    }
}

// ---------------- Kernel B: FA2-style HMMA attention ----------------------
// grid (KSPLIT, Nn/128, Bb), block 128 (4 warps, 32 queries each).
// Loader is pure copies (data pre-packed by proj).
__global__ __launch_bounds__(128) void attn_kernel()
{
    __shared__ __align__(16) uint32_t s_fh[2][CHK * 4];   // f_hi bf16x2: [key][4]
    __shared__ __align__(16) uint32_t s_fl[2][CHK * 4];   // f_lo
    __shared__ __align__(16) uint32_t s_hT[2][8 * 132];   // H^T fp16x2: 8 rows, 132 u32 stride

    const int t = threadIdx.x, wid = t >> 5, lane = t & 31;
    const int ks = blockIdx.x, qt = blockIdx.y, b = blockIdx.z;
    const int kbase = ks * KPC;
    const int r = lane >> 2, c2 = (lane & 3) * 2;
    const uint32_t ONES = 0x3C003C00u;   // fp16x2 {1,1}

    // G A-fragments (once): A[16q x 16] = [g_hi(8) | g_lo(8)] bf16
    uint32_t aG[2][4];
    #pragma unroll
    for (int mt = 0; mt < 2; mt++) {
        #pragma unroll
        for (int hh = 0; hh < 2; hh++) {
            const int q = qt * 128 + wid * 32 + mt * 16 + r + hh * 8;
            const float2 gv = *(const float2*)&d_g[((size_t)b * Nn + q) * 8 + c2];
            uint32_t hw, lw;
            pack_split(gv.x, gv.y, hw, lw);
            aG[mt][hh]     = hw;
            aG[mt][2 + hh] = lw;
        }
    }

    float vacc[2][4] = {{0.f,0.f,0.f,0.f},{0.f,0.f,0.f,0.f}};
    float dacc[2][4] = {{0.f,0.f,0.f,0.f},{0.f,0.f,0.f,0.f}};

    auto load_chunk = [&](int ch, int buf) {
        const size_t base = (size_t)b * Nn + kbase + ch * CHK;
        // F: keys t, t+128 — straight uint4 copies
        #pragma unroll
        for (int kk = 0; kk < 2; kk++) {
            const int key = t + kk * 128;
            const uint4* src = (const uint4*)&d_fpk[(base + key) * 8];
            *(uint4*)&s_fh[buf][key * 4] = src[0];
            *(uint4*)&s_fl[buf][key * 4] = src[1];
        }
        // H^T: 8 rows x 128 u32; thread t -> row t>>4, words (t&15)*8 .. +8
        {
            const int d = t >> 4, w = (t & 15) * 8;
            const uint4* hs = (const uint4*)((const uint32_t*)d_hT +
                                             (((size_t)d * BN + base) >> 1) + w);
            *(uint4*)&s_hT[buf][d * 132 + w]     = hs[0];
            *(uint4*)&s_hT[buf][d * 132 + w + 4] = hs[1];
        }
    };

    auto compute = [&](int buf) {
        #pragma unroll
        for (int g = 0; g < 16; g++) {         // 16-key groups
            #pragma unroll
            for (int mt = 0; mt < 2; mt++) {
                // S: two n8 tiles, exact via bf16 hi+lo; acc pre-biased -SHIFT
                float s[8] = {-SHIFT,-SHIFT,-SHIFT,-SHIFT,-SHIFT,-SHIFT,-SHIFT,-SHIFT};
                #pragma unroll
                for (int nt = 0; nt < 2; nt++) {
                    const int key = g * 16 + nt * 8 + r;
                    const uint32_t bh = s_fh[buf][key * 4 + (lane & 3)];
                    const uint32_t bl = s_fl[buf][key * 4 + (lane & 3)];
                    mma16816(&s[nt * 4], aG[mt], bh, bh);  // (gh+gl)*fh
                    mma16816(&s[nt * 4], aG[mt], bl, bl);  // (gh+gl)*fl
                }
                // p = 2^s (shift folded into accumulator bias)
                float p[8];
                #pragma unroll
                for (int j = 0; j < 8; j++) p[j] = ex2f(s[j]);
                // P A-fragment, fp16 satfinite
                uint32_t ap[4];
                ap[0] = pkf16s(p[0], p[1]);
                ap[1] = pkf16s(p[2], p[3]);
                ap[2] = pkf16s(p[4], p[5]);
                ap[3] = pkf16s(p[6], p[7]);
                // V: single fp16 MMA over 16 keys
                const int kw = g * 8 + (lane & 3);
                const uint32_t b0 = s_hT[buf][r * 132 + kw];
                const uint32_t b1 = s_hT[buf][r * 132 + kw + 4];
                mma16816h(vacc[mt], ap, b0, b1);
                // den: P row-sum via ones-B MMA (tensor pipe)
                mma16816h(dacc[mt], ap, ONES, ONES);
            }
        }
    };

    load_chunk(0, 0);
    __syncthreads();
    for (int ch = 0; ch < NCHK; ch++) {
        if (ch + 1 < NCHK) load_chunk(ch + 1, (ch + 1) & 1);  // LDGs overlap compute
        compute(ch & 1);
        __syncthreads();
    }

    // Epilogue: dacc holds full row-sums (all cols identical)
    const size_t base = ((size_t)ks * Bb + b) * Nn;
    #pragma unroll
    for (int mt = 0; mt < 2; mt++) {
        #pragma unroll
        for (int hh = 0; hh < 2; hh++) {
            const int q = qt * 128 + wid * 32 + mt * 16 + r + hh * 8;
            *(float2*)&d_pacc[(base + q) * 8 + c2] =
                make_float2(vacc[mt][2 * hh], vacc[mt][2 * hh + 1]);
            if ((lane & 3) == 0) d_pden[base + q] = dacc[mt][2 * hh];
        }
    }
}

// ---------------- Kernel C: combine splits, Wo projection, y ---------------
// grid (Nn/128, Bb), block 256: both halves combine 2 splits each.
__global__ __launch_bounds__(256) void out_kernel(
    const float* __restrict__ x,
    const float* __restrict__ Wo, const float* __restrict__ bo,
    const float* __restrict__ gamma, float* __restrict__ out)
{
    __shared__ float vs[8 * 128];
    __shared__ float red2[9][128];
    __shared__ float wos[512], bos[64];
    const int t = threadIdx.x, px = t & 127, half = t >> 7;
    const int b = blockIdx.y;
    const int m = blockIdx.x * 128 + px;

    for (int i = t; i < 512; i += 256) wos[i] = Wo[i];
    if (t < 64) bos[t] = bo[t];

    float acc[8] = {0, 0, 0, 0, 0, 0, 0, 0};
    float den = 0.0f;
    #pragma unroll
    for (int si = 0; si < 2; si++) {
        const int s = half * 2 + si;
        const size_t base = ((size_t)s * Bb + b) * Nn + m;
        const float4* pp = (const float4*)&d_pacc[base * 8];
        const float4 a0 = pp[0], a1 = pp[1];
        acc[0] += a0.x; acc[1] += a0.y; acc[2] += a0.z; acc[3] += a0.w;
        acc[4] += a1.x; acc[5] += a1.y; acc[6] += a1.z; acc[7] += a1.w;
        den += d_pden[base];
    }
    if (half == 1) {
        #pragma unroll
        for (int e = 0; e < 8; e++) red2[e][px] = acc[e];
        red2[8][px] = den;
    }
    __syncthreads();
    if (half == 0) {
        den += red2[8][px];
        const float inv = 1.0f / den;
        #pragma unroll
        for (int e = 0; e < 8; e++)
            vs[e * 128 + px] = (acc[e] + red2[e][px]) * inv;
    }
    __syncthreads();

    const float gam = gamma[0];
    #pragma unroll 4
    for (int ci = 0; ci < 32; ci++) {
        const int c = half * 32 + ci;
        float o = bos[c];
        #pragma unroll
        for (int e = 0; e < 8; e++) o = fmaf(wos[c * 8 + e], vs[e * 128 + px], o);
        const size_t idx = ((size_t)b * 64 + c) * Nn + m;
        out[BCN + idx] = o;
        out[idx]       = fmaf(gam, o, x[idx]);
    }
    if (b == 0 && m == 0 && half == 0) out[2 * BCN] = gam;
}

// ---------------- Launch ----------------------------------------------------
extern "C" void kernel_launch(void* const* d_in, const int* in_sizes, int n_in,
                              void* d_out, int out_size)
{
    const float* x     = (const float*)d_in[0];
    const float* Wk    = (const float*)d_in[1];
    const float* bk    = (const float*)d_in[2];
    const float* Wq    = (const float*)d_in[3];
    const float* bq    = (const float*)d_in[4];
    const float* Wv    = (const float*)d_in[5];
    const float* bv    = (const float*)d_in[6];
    const float* Wo    = (const float*)d_in[7];
    const float* bo    = (const float*)d_in[8];
    const float* gamma = (const float*)d_in[9];
    float* out = (float*)d_out;

    proj_kernel<<<dim3(Nn / 128, Bb), 256>>>(x, Wk, bk, Wq, bq, Wv, bv);
    attn_kernel<<<dim3(KSPLIT, Nn / 128, Bb), 128>>>();
    out_kernel<<<dim3(Nn / 128, Bb), 256>>>(x, Wo, bo, gamma, out);
}